// round 11
// baseline (speedup 1.0000x reference)
#include <cuda_runtime.h>
#include <cuda_fp16.h>
#include <math.h>
#include <stdint.h>

// Problem dims
#define BSZ   16
#define LSEQ  1024
#define HDIM  256
#define PDIM  256
#define MROWS (BSZ*LSEQ)     // 16384
#define N1    (2*PDIM)       // 512  (interleaved re/im: col 2p, 2p+1)
#define K1    HDIM           // 256
#define N3    HDIM           // 256
#define K3    (2*PDIM)       // 512
#define CHUNK 128            // == GEMM1 M-tile
#define NCH   (LSEQ/CHUNK)   // 8

// Scratch (static device memory; no allocations allowed)
__device__ __align__(128) __half g_S16[(size_t)MROWS * N1];  // 16 MB: final states fp16
__device__ __align__(128) __half g_u16[(size_t)MROWS * HDIM];// 8 MB: u in fp16
__device__ __align__(128) __half g_Wb16[N1 * K1];            // (512,256) N-major, K-contig
__device__ __align__(128) __half g_Wc16[N3 * K3];            // (256,512) N-major, K-contig
__device__ float2 g_coef[PDIM];                              // scaled (Lambda_bar-1)/Lambda
__device__ float g_lam_re[PDIM], g_lam_im[PDIM];
__device__ float g_lam32_re[PDIM], g_lam32_im[PDIM];         // lam^32   (fp64-exact)
__device__ float g_pow32_re[4][PDIM], g_pow32_im[4][PDIM];   // lam^(32q)
__device__ float g_powT_re[NCH][PDIM], g_powT_im[NCH][PDIM]; // lam^(128j)
__device__ float g_inv_scl[PDIM];
__device__ __align__(128) float    g_car[BSZ * NCH * PDIM * 2]; // chunk aggregates
__device__ __align__(128) unsigned g_flag[BSZ * NCH * PDIM];    // per-p publish flags

// ---------------------------------------------------------------------------
// helpers
// ---------------------------------------------------------------------------
__device__ __forceinline__ uint32_t smem_u32(const void* p) {
    uint32_t a;
    asm("{ .reg .u64 t; cvta.to.shared.u64 t, %1; cvt.u32.u64 %0, t; }" : "=r"(a) : "l"(p));
    return a;
}
__device__ __forceinline__ uint32_t f2h2(float a, float b) {   // lo=a, hi=b
    uint32_t r;
    asm("cvt.rn.f16x2.f32 %0, %1, %2;" : "=r"(r) : "f"(b), "f"(a));
    return r;
}
__device__ __forceinline__ void cp_async16(uint32_t saddr, const void* gaddr) {
    asm volatile("cp.async.cg.shared.global [%0], [%1], 16;" :: "r"(saddr), "l"(gaddr));
}
#define CP_COMMIT() asm volatile("cp.async.commit_group;" ::: "memory")
#define CP_WAIT(n)  asm volatile("cp.async.wait_group %0;" :: "n"(n) : "memory")

__device__ __forceinline__ void st_release_u32(unsigned* p, unsigned v) {
    asm volatile("st.release.gpu.global.u32 [%0], %1;" :: "l"(p), "r"(v) : "memory");
}
__device__ __forceinline__ unsigned ld_acquire_u32(const unsigned* p) {
    unsigned v;
    asm volatile("ld.acquire.gpu.global.u32 %0, [%1];" : "=r"(v) : "l"(p) : "memory");
    return v;
}
__device__ __forceinline__ float2 ld_relaxed_f2(const float* p) {
    float2 v;
    asm volatile("ld.relaxed.gpu.global.v2.f32 {%0,%1}, [%2];"
                 : "=f"(v.x), "=f"(v.y) : "l"(p) : "memory");
    return v;
}

__device__ __forceinline__ void ldsm4(uint32_t& r0, uint32_t& r1, uint32_t& r2,
                                      uint32_t& r3, uint32_t addr) {
    asm volatile("ldmatrix.sync.aligned.m8n8.x4.shared.b16 {%0,%1,%2,%3}, [%4];"
                 : "=r"(r0), "=r"(r1), "=r"(r2), "=r"(r3) : "r"(addr));
}
__device__ __forceinline__ void mma16816(float c[4], const uint32_t a[4],
                                         uint32_t b0, uint32_t b1) {
    asm volatile(
        "mma.sync.aligned.m16n8k16.row.col.f32.f16.f16.f32 "
        "{%0,%1,%2,%3}, {%4,%5,%6,%7}, {%8,%9}, {%0,%1,%2,%3};"
        : "+f"(c[0]), "+f"(c[1]), "+f"(c[2]), "+f"(c[3])
        : "r"(a[0]), "r"(a[1]), "r"(a[2]), "r"(a[3]), "r"(b0), "r"(b1));
}

// MMA block on one 32-k stage (validated layout: 64B rows, chunk^((row>>1)&3)).
#define MMA_STAGE(stgAddr)                                                    \
    do {                                                                      \
        _Pragma("unroll")                                                     \
        for (int ks = 0; ks < 2; ++ks) {                                      \
            const int cbase = ks * 2;                                         \
            uint32_t af[2][4];                                                \
            _Pragma("unroll")                                                 \
            for (int mi = 0; mi < 2; ++mi) {                                  \
                int ml = mBase + mi * 16 + (lane & 15);                       \
                int ci = (cbase + (lane >> 4)) ^ ((ml >> 1) & 3);             \
                ldsm4(af[mi][0], af[mi][1], af[mi][2], af[mi][3],             \
                      (stgAddr) + ml * 64 + ci * 16);                         \
            }                                                                 \
            uint32_t bf[4][4];                                                \
            _Pragma("unroll")                                                 \
            for (int nj = 0; nj < 4; ++nj) {                                  \
                int nl = nBase + nj * 16 + ((lane >> 4) & 1) * 8 + (lane & 7);\
                int ci = (cbase + ((lane >> 3) & 1)) ^ ((nl >> 1) & 3);       \
                ldsm4(bf[nj][0], bf[nj][1], bf[nj][2], bf[nj][3],             \
                      (stgAddr) + 8192 + nl * 64 + ci * 16);                  \
            }                                                                 \
            _Pragma("unroll")                                                 \
            for (int mi = 0; mi < 2; ++mi)                                    \
                _Pragma("unroll")                                             \
                for (int nj = 0; nj < 4; ++nj) {                              \
                    mma16816(acc[mi][nj * 2 + 0], af[mi], bf[nj][0], bf[nj][1]);\
                    mma16816(acc[mi][nj * 2 + 1], af[mi], bf[nj][2], bf[nj][3]);\
                }                                                             \
        }                                                                     \
    } while (0)

// ---------------------------------------------------------------------------
// Per-p fp64 constants (tiny: 256 threads total).  grid = 8, block = 32.
// ---------------------------------------------------------------------------
__global__ void s5_const_kernel(const float* __restrict__ Lre,
                                const float* __restrict__ Lim,
                                const float* __restrict__ lstep)
{
    int p = blockIdx.x * 32 + threadIdx.x;

    double lre = (double)Lre[p], lim = (double)Lim[p];
    double delta = exp((double)lstep[p]);
    double a = lre * delta, b = lim * delta;
    double ea = exp(a);
    double lam_r = ea * cos(b);
    double lam_i = ea * sin(b);
    double d2 = lre * lre + lim * lim;
    double nr = lam_r - 1.0, ni = lam_i;
    double cr = (nr * lre + ni * lim) / d2;
    double ci = (ni * lre - nr * lim) / d2;

    int e;
    frexp(sqrt(cr * cr + ci * ci), &e);
    double scl = ldexp(1.0, -e);
    g_coef[p] = make_float2((float)(cr * scl), (float)(ci * scl));
    g_inv_scl[p] = (float)ldexp(1.0, e);

    g_lam_re[p] = (float)lam_r;
    g_lam_im[p] = (float)lam_i;
    {
        double a32 = a * 32.0, b32 = b * 32.0;
        double e32 = exp(a32);
        g_lam32_re[p] = (float)(e32 * cos(b32));
        g_lam32_im[p] = (float)(e32 * sin(b32));
    }
#pragma unroll
    for (int q = 0; q < 4; ++q) {       // lam^(32q)
        double aq = a * 32.0 * q, bq = b * 32.0 * q;
        double eq = exp(aq);
        g_pow32_re[q][p] = (float)(eq * cos(bq));
        g_pow32_im[q][p] = (float)(eq * sin(bq));
    }
#pragma unroll
    for (int j = 0; j < NCH; ++j) {     // lam^(128j)
        double aT = a * (double)(CHUNK * j), bT = b * (double)(CHUNK * j);
        double eT = exp(aT);
        g_powT_re[j][p] = (float)(eT * cos(bT));
        g_powT_im[j][p] = (float)(eT * sin(bT));
    }
}

// ---------------------------------------------------------------------------
// Fused u->fp16 + flag clear + fp16 weight packing.
// Blocks [0,2048): u conversion (8 floats/thread).  Blocks [2048,2304):
// weight packing (p = blockIdx-2048, h = threadIdx).  grid = 2304, block 256.
// ---------------------------------------------------------------------------
__global__ void s5_prep_kernel(const float* __restrict__ u,
                               const float* __restrict__ Bp,
                               const float* __restrict__ Cp)
{
    if (blockIdx.x < 2048) {
        size_t i = ((size_t)blockIdx.x * 256 + threadIdx.x) * 8;
        float4 a = *(const float4*)(u + i);
        float4 b = *(const float4*)(u + i + 4);
        *(uint4*)(g_u16 + i) = make_uint4(f2h2(a.x, a.y), f2h2(a.z, a.w),
                                          f2h2(b.x, b.y), f2h2(b.z, b.w));
        if (blockIdx.x < 32) {   // clear 32768 flags (8192 uint4)
            ((uint4*)g_flag)[blockIdx.x * 256 + threadIdx.x] =
                make_uint4(0u, 0u, 0u, 0u);
        }
    } else {
        int p = blockIdx.x - 2048;
        int h = threadIdx.x;
        float2 cf = g_coef[p];

        float br = Bp[((size_t)p * HDIM + h) * 2 + 0];
        float bi = Bp[((size_t)p * HDIM + h) * 2 + 1];
        g_Wb16[(size_t)(2 * p) * K1 + h]     = __float2half(cf.x * br - cf.y * bi);
        g_Wb16[(size_t)(2 * p + 1) * K1 + h] = __float2half(cf.x * bi + cf.y * br);

        float ccr = Cp[((size_t)h * PDIM + p) * 2 + 0];
        float cci = Cp[((size_t)h * PDIM + p) * 2 + 1];
        g_Wc16[(size_t)h * K3 + 2 * p]     = __float2half( 2.0f * ccr);
        g_Wc16[(size_t)h * K3 + 2 * p + 1] = __float2half(-2.0f * cci);
    }
}

// ---------------------------------------------------------------------------
// GEMM1 + fused FULL scan (chunk-local + decoupled-lookback cross-chunk).
// k=32 stages, 4-stage cp.async ring, occupancy-3 launch bounds.
// Writes final states fp16 directly to g_S16.
// ---------------------------------------------------------------------------
#define G1_SMEM 70656   // max(65536 pipeline, 66560 Stile + 4096 carries)

__global__ void __launch_bounds__(256, 3)
s5_gemm1_scan()
{
    extern __shared__ char sm[];
    uint32_t sb = smem_u32(sm);

    const int t = threadIdx.x;
    const int lane = t & 31, w = t >> 5;
    const int g = lane >> 2, tig = lane & 3;
    const int mBase = (w & 3) * 32;
    const int nBase = (w >> 2) * 64;
    const int m0 = blockIdx.y * 128, n0 = blockIdx.x * 128;
    const int bIdx = m0 >> 10, cIdx = (m0 >> 7) & (NCH - 1);

    const int r0 = t >> 2, c0 = t & 3;
    const uint32_t sAoff = r0 * 64 + (((uint32_t)(c0 ^ ((r0 >> 1) & 3))) << 4);
    const __half* Ag = g_u16 + (size_t)(m0 + r0) * K1 + c0 * 8;
    const __half* Bg = g_Wb16 + (size_t)(n0 + r0) * K1 + c0 * 8;

    auto issue = [&](int slot, int kof) {
        uint32_t base = sb + slot * 16384;
        cp_async16(base + sAoff,        Ag + kof);
        cp_async16(base + sAoff + 4096, Ag + kof + (size_t)64 * K1);
        cp_async16(base + sAoff + 8192, Bg + kof);
        cp_async16(base + sAoff + 12288,Bg + kof + (size_t)64 * K1);
    };

    float acc[2][8][4];
#pragma unroll
    for (int mi = 0; mi < 2; ++mi)
#pragma unroll
        for (int ni = 0; ni < 8; ++ni)
#pragma unroll
            for (int q = 0; q < 4; ++q) acc[mi][ni][q] = 0.0f;

    issue(0, 0);  CP_COMMIT();
    issue(1, 32); CP_COMMIT();
    issue(2, 64); CP_COMMIT();

    const int NIT = K1 / 32;   // 8
    for (int it = 0; it < NIT; ++it) {
        CP_WAIT(2);
        __syncthreads();
        uint32_t stg = sb + (it & 3) * 16384;
        MMA_STAGE(stg);
        if (it + 3 < NIT) issue((it + 3) & 3, (it + 3) * 32);
        CP_COMMIT();
    }
    CP_WAIT(0);
    __syncthreads();   // pipeline smem dead; reuse as Stile

    float* Stile = (float*)sm;              // 128 x 130
    float* carrR = (float*)(sm + 66560);    // [4][64]  (later: E_chunk [64])
    float* carrI = carrR + 256;
    float* prefR = carrI + 256;             // [4][64]
    float* prefI = prefR + 256;

    // 1. accs -> Stile
#pragma unroll
    for (int mi = 0; mi < 2; ++mi) {
        int row = mBase + mi * 16 + g;
#pragma unroll
        for (int ni = 0; ni < 8; ++ni) {
            int col = nBase + ni * 8 + 2 * tig;
            *(float2*)(Stile + row * 130 + col) =
                make_float2(acc[mi][ni][0], acc[mi][ni][1]);
            *(float2*)(Stile + (row + 8) * 130 + col) =
                make_float2(acc[mi][ni][2], acc[mi][ni][3]);
        }
    }
    __syncthreads();

    // 2. segment-local scan (zero init), 4 segs x 64 complex cols
    const int pl = t & 63, seg = t >> 6;
    const int pg = (n0 >> 1) + pl;
    const float lr = g_lam_re[pg], li = g_lam_im[pg];
    {
        float yr = 0.f, yi = 0.f;
        float* colp = Stile + 2 * pl;
#pragma unroll 4
        for (int tt = 0; tt < 32; ++tt) {
            int row = seg * 32 + tt;
            float2 s = *(float2*)(colp + row * 130);
            float nyr = fmaf(lr, yr, fmaf(-li, yi, s.x));
            float nyi = fmaf(lr, yi, fmaf( li, yr, s.y));
            yr = nyr; yi = nyi;
            *(float2*)(colp + row * 130) = make_float2(yr, yi);
        }
        carrR[seg * 64 + pl] = yr;
        carrI[seg * 64 + pl] = yi;
    }
    __syncthreads();

    // 3. seg-carry combine (lam^32) -> chunk aggregate; publish (release);
    //    lookback: fold predecessors' aggregates into E_chunk (acquire).
    if (t < 64) {
        int pg2 = (n0 >> 1) + t;
        float l32r = g_lam32_re[pg2], l32i = g_lam32_im[pg2];
        float Pr = 0.f, Pi = 0.f;
        float sp[4][2];
#pragma unroll
        for (int q = 0; q < 4; ++q) {
            sp[q][0] = Pr; sp[q][1] = Pi;
            float cr = carrR[q * 64 + t], ci = carrI[q * 64 + t];
            float nPr = fmaf(l32r, Pr, fmaf(-l32i, Pi, cr));
            float nPi = fmaf(l32r, Pi, fmaf( l32i, Pr, ci));
            Pr = nPr; Pi = nPi;
        }
        // publish chunk aggregate
        size_t ci0 = (size_t)(bIdx * NCH + cIdx) * PDIM + pg2;
        *(float2*)(g_car + 2 * ci0) = make_float2(Pr, Pi);
        st_release_u32(g_flag + ci0, 1u);

        // lookback over earlier chunks (independent aggregates, no chaining)
        float Ecr = 0.f, Eci = 0.f;
        for (int j = 0; j < cIdx; ++j) {
            int d = cIdx - 1 - j;
            size_t fj = (size_t)(bIdx * NCH + j) * PDIM + pg2;
            while (ld_acquire_u32(g_flag + fj) == 0) { }
            float2 cv = ld_relaxed_f2(g_car + 2 * fj);
            float pr = g_powT_re[d][pg2], pi = g_powT_im[d][pg2];
            Ecr = fmaf(pr, cv.x, fmaf(-pi, cv.y, Ecr));
            Eci = fmaf(pr, cv.y, fmaf( pi, cv.x, Eci));
        }
#pragma unroll
        for (int q = 0; q < 4; ++q) {
            prefR[q * 64 + t] = sp[q][0];
            prefI[q * 64 + t] = sp[q][1];
        }
        carrR[t] = Ecr;   // reuse smem for E_chunk
        carrI[t] = Eci;
    }
    __syncthreads();

    // 4. total prefix apply + fp16 convert, write final states to g_S16
    {
        float Ecr = carrR[pl], Eci = carrI[pl];
        float p32r = g_pow32_re[seg][pg], p32i = g_pow32_im[seg][pg];
        float Er = prefR[seg * 64 + pl] + p32r * Ecr - p32i * Eci;
        float Ei = prefI[seg * 64 + pl] + p32r * Eci + p32i * Ecr;
        float inv = g_inv_scl[pg];
        float wr = lr, wi = li;
        float* colp = Stile + 2 * pl;
        __half2* op = (__half2*)g_S16 + (size_t)m0 * PDIM + pg;
#pragma unroll 4
        for (int tt = 0; tt < 32; ++tt) {
            int row = seg * 32 + tt;
            float2 s = *(float2*)(colp + row * 130);
            float xr = fmaf(wr, Er, fmaf(-wi, Ei, s.x));
            float xi = fmaf(wr, Ei, fmaf( wi, Er, s.y));
            op[(size_t)row * PDIM] = __floats2half2_rn(xr * inv, xi * inv);
            float nwr = fmaf(wr, lr, -wi * li);
            float nwi = fmaf(wr, li,  wi * lr);
            wr = nwr; wi = nwi;
        }
    }
}

// ---------------------------------------------------------------------------
// GEMM3: C = S16 @ Wc16^T + D*u.  k=32, 4-stage ring, occupancy-3 bounds.
// ---------------------------------------------------------------------------
#define G3_SMEM 65536

__global__ void __launch_bounds__(256, 3)
s5_gemm3(float* __restrict__ C,
         const float* __restrict__ Dvec,
         const float* __restrict__ U)
{
    extern __shared__ char sm[];
    uint32_t sb = smem_u32(sm);

    const int t = threadIdx.x;
    const int lane = t & 31, w = t >> 5;
    const int g = lane >> 2, tig = lane & 3;
    const int mBase = (w & 3) * 32;
    const int nBase = (w >> 2) * 64;
    const int m0 = blockIdx.y * 128, n0 = blockIdx.x * 128;

    const int r0 = t >> 2, c0 = t & 3;
    const uint32_t sAoff = r0 * 64 + (((uint32_t)(c0 ^ ((r0 >> 1) & 3))) << 4);
    const __half* Ag = g_S16 + (size_t)(m0 + r0) * K3 + c0 * 8;
    const __half* Bg = g_Wc16 + (size_t)(n0 + r0) * K3 + c0 * 8;

    auto issue = [&](int slot, int kof) {
        uint32_t base = sb + slot * 16384;
        cp_async16(base + sAoff,        Ag + kof);
        cp_async16(base + sAoff + 4096, Ag + kof + (size_t)64 * K3);
        cp_async16(base + sAoff + 8192, Bg + kof);
        cp_async16(base + sAoff + 12288,Bg + kof + (size_t)64 * K3);
    };

    float acc[2][8][4];
#pragma unroll
    for (int mi = 0; mi < 2; ++mi)
#pragma unroll
        for (int ni = 0; ni < 8; ++ni)
#pragma unroll
            for (int q = 0; q < 4; ++q) acc[mi][ni][q] = 0.0f;

    issue(0, 0);  CP_COMMIT();
    issue(1, 32); CP_COMMIT();
    issue(2, 64); CP_COMMIT();

    const int NIT = K3 / 32;   // 16
    for (int it = 0; it < NIT; ++it) {
        CP_WAIT(2);
        __syncthreads();
        uint32_t stg = sb + (it & 3) * 16384;
        MMA_STAGE(stg);
        if (it + 3 < NIT) issue((it + 3) & 3, (it + 3) * 32);
        CP_COMMIT();
    }

    // Epilogue with D*u feedthrough
#pragma unroll
    for (int mi = 0; mi < 2; ++mi) {
        int row0 = m0 + mBase + mi * 16 + g;
#pragma unroll
        for (int ni = 0; ni < 8; ++ni) {
            int col = n0 + nBase + ni * 8 + 2 * tig;
            float d0 = Dvec[col], d1 = Dvec[col + 1];
            float2 u0 = *(const float2*)(U + (size_t)row0 * HDIM + col);
            float2 u1 = *(const float2*)(U + (size_t)(row0 + 8) * HDIM + col);
            float2 v0 = make_float2(fmaf(d0, u0.x, acc[mi][ni][0]),
                                    fmaf(d1, u0.y, acc[mi][ni][1]));
            float2 v1 = make_float2(fmaf(d0, u1.x, acc[mi][ni][2]),
                                    fmaf(d1, u1.y, acc[mi][ni][3]));
            *(float2*)(C + (size_t)row0 * N3 + col) = v0;
            *(float2*)(C + (size_t)(row0 + 8) * N3 + col) = v1;
        }
    }
}

// ---------------------------------------------------------------------------
extern "C" void kernel_launch(void* const* d_in, const int* in_sizes, int n_in,
                              void* d_out, int out_size)
{
    const float* u   = (const float*)d_in[0];
    const float* Lre = (const float*)d_in[1];
    const float* Lim = (const float*)d_in[2];
    const float* Bp  = (const float*)d_in[3];
    const float* Cp  = (const float*)d_in[4];
    const float* Dv  = (const float*)d_in[5];
    const float* lst = (const float*)d_in[6];
    float* out = (float*)d_out;

    cudaFuncSetAttribute(s5_gemm1_scan,
                         cudaFuncAttributeMaxDynamicSharedMemorySize, G1_SMEM);
    cudaFuncSetAttribute(s5_gemm3,
                         cudaFuncAttributeMaxDynamicSharedMemorySize, G3_SMEM);

    // 1. per-p fp64 constants (tiny); fused u->fp16 + flags + weight packing
    s5_const_kernel<<<8, 32>>>(Lre, Lim, lst);
    s5_prep_kernel<<<2304, 256>>>(u, Bp, Cp);

    // 2. Bu GEMM + fused full scan (lookback) -> final states fp16 (g_S16)
    s5_gemm1_scan<<<dim3(N1 / 128, MROWS / 128), 256, G1_SMEM>>>();

    // 3. y = states16 @ Wc16^T + D*u
    s5_gemm3<<<dim3(N3 / 128, MROWS / 128), 256, G3_SMEM>>>(out, Dv, u);
}

// round 12
// speedup vs baseline: 1.0505x; 1.0505x over previous
#include <cuda_runtime.h>
#include <cuda_fp16.h>
#include <math.h>
#include <stdint.h>

// Problem dims
#define BSZ   16
#define LSEQ  1024
#define HDIM  256
#define PDIM  256
#define MROWS (BSZ*LSEQ)     // 16384
#define N1    (2*PDIM)       // 512  (interleaved re/im: col 2p, 2p+1)
#define K1    HDIM           // 256
#define N3    HDIM           // 256
#define K3    (2*PDIM)       // 512
#define CHUNK 128            // == GEMM1 M-tile
#define NCH   (LSEQ/CHUNK)   // 8

// Scratch (static device memory; no allocations allowed)
__device__ __align__(128) __half g_S16[(size_t)MROWS * N1];  // 16 MB: final states fp16
__device__ __align__(128) __half g_u16[(size_t)MROWS * HDIM];// 8 MB: u in fp16
__device__ __align__(128) __half g_Wb16[N1 * K1];            // (512,256) N-major, K-contig
__device__ __align__(128) __half g_Wc16[N3 * K3];            // (256,512) N-major, K-contig
__device__ float g_lam_re[PDIM], g_lam_im[PDIM];
__device__ float g_lam32_re[PDIM], g_lam32_im[PDIM];         // lam^32   (fp64-exact)
__device__ float g_pow32_re[4][PDIM], g_pow32_im[4][PDIM];   // lam^(32q)
__device__ float g_powT_re[NCH][PDIM], g_powT_im[NCH][PDIM]; // lam^(128j)
__device__ float g_inv_scl[PDIM];
__device__ __align__(128) float    g_car[BSZ * NCH * PDIM * 2]; // chunk aggregates
__device__ __align__(128) unsigned g_flag[BSZ * NCH * PDIM];    // per-p publish flags

// ---------------------------------------------------------------------------
// helpers
// ---------------------------------------------------------------------------
__device__ __forceinline__ uint32_t smem_u32(const void* p) {
    uint32_t a;
    asm("{ .reg .u64 t; cvta.to.shared.u64 t, %1; cvt.u32.u64 %0, t; }" : "=r"(a) : "l"(p));
    return a;
}
__device__ __forceinline__ uint32_t f2h2(float a, float b) {   // lo=a, hi=b
    uint32_t r;
    asm("cvt.rn.f16x2.f32 %0, %1, %2;" : "=r"(r) : "f"(b), "f"(a));
    return r;
}
__device__ __forceinline__ void cp_async16(uint32_t saddr, const void* gaddr) {
    asm volatile("cp.async.cg.shared.global [%0], [%1], 16;" :: "r"(saddr), "l"(gaddr));
}
#define CP_COMMIT() asm volatile("cp.async.commit_group;" ::: "memory")
#define CP_WAIT(n)  asm volatile("cp.async.wait_group %0;" :: "n"(n) : "memory")

__device__ __forceinline__ void st_release_u32(unsigned* p, unsigned v) {
    asm volatile("st.release.gpu.global.u32 [%0], %1;" :: "l"(p), "r"(v) : "memory");
}
__device__ __forceinline__ unsigned ld_acquire_u32(const unsigned* p) {
    unsigned v;
    asm volatile("ld.acquire.gpu.global.u32 %0, [%1];" : "=r"(v) : "l"(p) : "memory");
    return v;
}
__device__ __forceinline__ float2 ld_relaxed_f2(const float* p) {
    float2 v;
    asm volatile("ld.relaxed.gpu.global.v2.f32 {%0,%1}, [%2];"
                 : "=f"(v.x), "=f"(v.y) : "l"(p) : "memory");
    return v;
}

__device__ __forceinline__ void ldsm4(uint32_t& r0, uint32_t& r1, uint32_t& r2,
                                      uint32_t& r3, uint32_t addr) {
    asm volatile("ldmatrix.sync.aligned.m8n8.x4.shared.b16 {%0,%1,%2,%3}, [%4];"
                 : "=r"(r0), "=r"(r1), "=r"(r2), "=r"(r3) : "r"(addr));
}
__device__ __forceinline__ void mma16816(float c[4], const uint32_t a[4],
                                         uint32_t b0, uint32_t b1) {
    asm volatile(
        "mma.sync.aligned.m16n8k16.row.col.f32.f16.f16.f32 "
        "{%0,%1,%2,%3}, {%4,%5,%6,%7}, {%8,%9}, {%0,%1,%2,%3};"
        : "+f"(c[0]), "+f"(c[1]), "+f"(c[2]), "+f"(c[3])
        : "r"(a[0]), "r"(a[1]), "r"(a[2]), "r"(a[3]), "r"(b0), "r"(b1));
}

// MMA block on one 32-k stage (fragment maps validated rounds 5-8).
#define MMA_STAGE(stgAddr)                                                    \
    do {                                                                      \
        _Pragma("unroll")                                                     \
        for (int ks = 0; ks < 2; ++ks) {                                      \
            const int cbase = ks * 2;                                         \
            uint32_t af[2][4];                                                \
            _Pragma("unroll")                                                 \
            for (int mi = 0; mi < 2; ++mi) {                                  \
                int ml = mBase + mi * 16 + (lane & 15);                       \
                int ci = (cbase + (lane >> 4)) ^ ((ml >> 1) & 3);             \
                ldsm4(af[mi][0], af[mi][1], af[mi][2], af[mi][3],             \
                      (stgAddr) + ml * 64 + ci * 16);                         \
            }                                                                 \
            uint32_t bf[4][4];                                                \
            _Pragma("unroll")                                                 \
            for (int nj = 0; nj < 4; ++nj) {                                  \
                int nl = nBase + nj * 16 + ((lane >> 4) & 1) * 8 + (lane & 7);\
                int ci = (cbase + ((lane >> 3) & 1)) ^ ((nl >> 1) & 3);       \
                ldsm4(bf[nj][0], bf[nj][1], bf[nj][2], bf[nj][3],             \
                      (stgAddr) + 8192 + nl * 64 + ci * 16);                  \
            }                                                                 \
            _Pragma("unroll")                                                 \
            for (int mi = 0; mi < 2; ++mi)                                    \
                _Pragma("unroll")                                             \
                for (int nj = 0; nj < 4; ++nj) {                              \
                    mma16816(acc[mi][nj * 2 + 0], af[mi], bf[nj][0], bf[nj][1]);\
                    mma16816(acc[mi][nj * 2 + 1], af[mi], bf[nj][2], bf[nj][3]);\
                }                                                             \
        }                                                                     \
    } while (0)

// ---------------------------------------------------------------------------
// u -> fp16 conversion + flag clear (one-shot).  grid = 2048, block = 256.
// ---------------------------------------------------------------------------
__global__ void s5_u2h_kernel(const float* __restrict__ u)
{
    size_t i = ((size_t)blockIdx.x * 256 + threadIdx.x) * 8;
    float4 a = *(const float4*)(u + i);
    float4 b = *(const float4*)(u + i + 4);
    *(uint4*)(g_u16 + i) = make_uint4(f2h2(a.x, a.y), f2h2(a.z, a.w),
                                      f2h2(b.x, b.y), f2h2(b.z, b.w));
    if (blockIdx.x < 32) {   // clear 32768 flags (8192 uint4)
        ((uint4*)g_flag)[blockIdx.x * 256 + threadIdx.x] =
            make_uint4(0u, 0u, 0u, 0u);
    }
}

// ---------------------------------------------------------------------------
// Setup: discretization, fp16 weight packing, fp64-exact power tables,
// per-p power-of-2 prescale of Wb.  grid = PDIM, block = HDIM.
// ---------------------------------------------------------------------------
__global__ void s5_setup_kernel(const float* __restrict__ Lre,
                                const float* __restrict__ Lim,
                                const float* __restrict__ Bp,
                                const float* __restrict__ Cp,
                                const float* __restrict__ lstep)
{
    int p = blockIdx.x;
    int h = threadIdx.x;

    double lre = (double)Lre[p], lim = (double)Lim[p];
    double delta = exp((double)lstep[p]);
    double a = lre * delta, b = lim * delta;
    double ea = exp(a);
    double lam_r = ea * cos(b);
    double lam_i = ea * sin(b);
    double d2 = lre * lre + lim * lim;
    double nr = lam_r - 1.0, ni = lam_i;
    double cr = (nr * lre + ni * lim) / d2;
    double ci = (ni * lre - nr * lim) / d2;

    int e;
    frexp(sqrt(cr * cr + ci * ci), &e);
    double scl = ldexp(1.0, -e);
    cr *= scl; ci *= scl;

    float br = Bp[((size_t)p * HDIM + h) * 2 + 0];
    float bi = Bp[((size_t)p * HDIM + h) * 2 + 1];
    g_Wb16[(size_t)(2 * p) * K1 + h]     = __float2half((float)(cr * br - ci * bi));
    g_Wb16[(size_t)(2 * p + 1) * K1 + h] = __float2half((float)(cr * bi + ci * br));

    float ccr = Cp[((size_t)h * PDIM + p) * 2 + 0];
    float cci = Cp[((size_t)h * PDIM + p) * 2 + 1];
    g_Wc16[(size_t)h * K3 + 2 * p]     = __float2half( 2.0f * ccr);
    g_Wc16[(size_t)h * K3 + 2 * p + 1] = __float2half(-2.0f * cci);

    if (h == 0) {
        g_lam_re[p] = (float)lam_r;
        g_lam_im[p] = (float)lam_i;
        g_inv_scl[p] = (float)ldexp(1.0, e);
        double a32 = a * 32.0, b32 = b * 32.0;
        double e32 = exp(a32);
        g_lam32_re[p] = (float)(e32 * cos(b32));
        g_lam32_im[p] = (float)(e32 * sin(b32));
    }
    if (h < 4) {   // lam^(32h)
        double aq = a * 32.0 * h, bq = b * 32.0 * h;
        double eq = exp(aq);
        g_pow32_re[h][p] = (float)(eq * cos(bq));
        g_pow32_im[h][p] = (float)(eq * sin(bq));
    }
    if (h < NCH) { // lam^(128h)
        double aT = a * (double)(CHUNK * h), bT = b * (double)(CHUNK * h);
        double eaT = exp(aT);
        g_powT_re[h][p] = (float)(eaT * cos(bT));
        g_powT_im[h][p] = (float)(eaT * sin(bT));
    }
}

// ---------------------------------------------------------------------------
// GEMM1 + fused FULL scan (chunk-local + decoupled-lookback cross-chunk).
// Writes final states fp16 directly to g_S16.  cp.async 4-stage pipeline.
// ---------------------------------------------------------------------------
#define G1_SMEM 70656   // max(65536 pipeline, 66560 Stile + 4096 carries)

__global__ void __launch_bounds__(256)
s5_gemm1_scan()
{
    extern __shared__ char sm[];
    uint32_t sb = smem_u32(sm);

    const int t = threadIdx.x;
    const int lane = t & 31, w = t >> 5;
    const int g = lane >> 2, tig = lane & 3;
    const int mBase = (w & 3) * 32;
    const int nBase = (w >> 2) * 64;
    const int m0 = blockIdx.y * 128, n0 = blockIdx.x * 128;
    const int bIdx = m0 >> 10, cIdx = (m0 >> 7) & (NCH - 1);

    const int r0 = t >> 2, c0 = t & 3;
    const uint32_t sAoff = r0 * 64 + (((uint32_t)(c0 ^ ((r0 >> 1) & 3))) << 4);
    const __half* Ag = g_u16 + (size_t)(m0 + r0) * K1 + c0 * 8;
    const __half* Bg = g_Wb16 + (size_t)(n0 + r0) * K1 + c0 * 8;

    auto issue = [&](int slot, int kof) {
        uint32_t base = sb + slot * 16384;
        cp_async16(base + sAoff,        Ag + kof);
        cp_async16(base + sAoff + 4096, Ag + kof + (size_t)64 * K1);
        cp_async16(base + sAoff + 8192, Bg + kof);
        cp_async16(base + sAoff + 12288,Bg + kof + (size_t)64 * K1);
    };

    float acc[2][8][4];
#pragma unroll
    for (int mi = 0; mi < 2; ++mi)
#pragma unroll
        for (int ni = 0; ni < 8; ++ni)
#pragma unroll
            for (int q = 0; q < 4; ++q) acc[mi][ni][q] = 0.0f;

    issue(0, 0);  CP_COMMIT();
    issue(1, 32); CP_COMMIT();
    issue(2, 64); CP_COMMIT();

    const int NIT = K1 / 32;   // 8
    for (int it = 0; it < NIT; ++it) {
        CP_WAIT(2);
        __syncthreads();
        uint32_t stg = sb + (it & 3) * 16384;
        MMA_STAGE(stg);
        if (it + 3 < NIT) issue((it + 3) & 3, (it + 3) * 32);
        CP_COMMIT();
    }
    CP_WAIT(0);
    __syncthreads();   // pipeline smem dead; reuse as Stile

    float* Stile = (float*)sm;              // 128 x 130
    float* carrR = (float*)(sm + 66560);    // [4][64]  (later: E_chunk [64])
    float* carrI = carrR + 256;
    float* prefR = carrI + 256;             // [4][64]
    float* prefI = prefR + 256;

    // 1. accs -> Stile
#pragma unroll
    for (int mi = 0; mi < 2; ++mi) {
        int row = mBase + mi * 16 + g;
#pragma unroll
        for (int ni = 0; ni < 8; ++ni) {
            int col = nBase + ni * 8 + 2 * tig;
            *(float2*)(Stile + row * 130 + col) =
                make_float2(acc[mi][ni][0], acc[mi][ni][1]);
            *(float2*)(Stile + (row + 8) * 130 + col) =
                make_float2(acc[mi][ni][2], acc[mi][ni][3]);
        }
    }
    __syncthreads();

    // 2. segment-local scan (zero init), 4 segs x 64 complex cols
    const int pl = t & 63, seg = t >> 6;
    const int pg = (n0 >> 1) + pl;
    const float lr = g_lam_re[pg], li = g_lam_im[pg];
    {
        float yr = 0.f, yi = 0.f;
        float* colp = Stile + 2 * pl;
#pragma unroll 4
        for (int tt = 0; tt < 32; ++tt) {
            int row = seg * 32 + tt;
            float2 s = *(float2*)(colp + row * 130);
            float nyr = fmaf(lr, yr, fmaf(-li, yi, s.x));
            float nyi = fmaf(lr, yi, fmaf( li, yr, s.y));
            yr = nyr; yi = nyi;
            *(float2*)(colp + row * 130) = make_float2(yr, yi);
        }
        carrR[seg * 64 + pl] = yr;
        carrI[seg * 64 + pl] = yi;
    }
    __syncthreads();

    // 3. seg-carry combine (lam^32) -> chunk aggregate; publish (release);
    //    lookback: fold predecessors' aggregates into E_chunk (acquire).
    if (t < 64) {
        int pg2 = (n0 >> 1) + t;
        float l32r = g_lam32_re[pg2], l32i = g_lam32_im[pg2];
        float Pr = 0.f, Pi = 0.f;
        float sp[4][2];
#pragma unroll
        for (int q = 0; q < 4; ++q) {
            sp[q][0] = Pr; sp[q][1] = Pi;
            float cr = carrR[q * 64 + t], ci = carrI[q * 64 + t];
            float nPr = fmaf(l32r, Pr, fmaf(-l32i, Pi, cr));
            float nPi = fmaf(l32r, Pi, fmaf( l32i, Pr, ci));
            Pr = nPr; Pi = nPi;
        }
        // publish chunk aggregate
        size_t ci0 = (size_t)(bIdx * NCH + cIdx) * PDIM + pg2;
        *(float2*)(g_car + 2 * ci0) = make_float2(Pr, Pi);
        st_release_u32(g_flag + ci0, 1u);

        // lookback over earlier chunks (independent aggregates, no chaining)
        float Ecr = 0.f, Eci = 0.f;
        for (int j = 0; j < cIdx; ++j) {
            int d = cIdx - 1 - j;
            size_t fj = (size_t)(bIdx * NCH + j) * PDIM + pg2;
            while (ld_acquire_u32(g_flag + fj) == 0) { }
            float2 cv = ld_relaxed_f2(g_car + 2 * fj);
            float pr = g_powT_re[d][pg2], pi = g_powT_im[d][pg2];
            Ecr = fmaf(pr, cv.x, fmaf(-pi, cv.y, Ecr));
            Eci = fmaf(pr, cv.y, fmaf( pi, cv.x, Eci));
        }
#pragma unroll
        for (int q = 0; q < 4; ++q) {
            prefR[q * 64 + t] = sp[q][0];
            prefI[q * 64 + t] = sp[q][1];
        }
        carrR[t] = Ecr;   // reuse smem for E_chunk
        carrI[t] = Eci;
    }
    __syncthreads();

    // 4. total prefix apply + fp16 convert, write final states to g_S16
    {
        float Ecr = carrR[pl], Eci = carrI[pl];
        float p32r = g_pow32_re[seg][pg], p32i = g_pow32_im[seg][pg];
        float Er = prefR[seg * 64 + pl] + p32r * Ecr - p32i * Eci;
        float Ei = prefI[seg * 64 + pl] + p32r * Eci + p32i * Ecr;
        float inv = g_inv_scl[pg];
        float wr = lr, wi = li;
        float* colp = Stile + 2 * pl;
        __half2* op = (__half2*)g_S16 + (size_t)m0 * PDIM + pg;
#pragma unroll 4
        for (int tt = 0; tt < 32; ++tt) {
            int row = seg * 32 + tt;
            float2 s = *(float2*)(colp + row * 130);
            float xr = fmaf(wr, Er, fmaf(-wi, Ei, s.x));
            float xi = fmaf(wr, Ei, fmaf( wi, Er, s.y));
            op[(size_t)row * PDIM] = __floats2half2_rn(xr * inv, xi * inv);
            float nwr = fmaf(wr, lr, -wi * li);
            float nwi = fmaf(wr, li,  wi * lr);
            wr = nwr; wi = nwi;
        }
    }
}

// ---------------------------------------------------------------------------
// GEMM3: C = S16 @ Wc16^T + D*u.  cp.async 4-stage pipeline, fused epilogue.
// ---------------------------------------------------------------------------
#define G3_SMEM 65536

__global__ void __launch_bounds__(256)
s5_gemm3(float* __restrict__ C,
         const float* __restrict__ Dvec,
         const float* __restrict__ U)
{
    extern __shared__ char sm[];
    uint32_t sb = smem_u32(sm);

    const int t = threadIdx.x;
    const int lane = t & 31, w = t >> 5;
    const int g = lane >> 2, tig = lane & 3;
    const int mBase = (w & 3) * 32;
    const int nBase = (w >> 2) * 64;
    const int m0 = blockIdx.y * 128, n0 = blockIdx.x * 128;

    const int r0 = t >> 2, c0 = t & 3;
    const uint32_t sAoff = r0 * 64 + (((uint32_t)(c0 ^ ((r0 >> 1) & 3))) << 4);
    const __half* Ag = g_S16 + (size_t)(m0 + r0) * K3 + c0 * 8;
    const __half* Bg = g_Wc16 + (size_t)(n0 + r0) * K3 + c0 * 8;

    auto issue = [&](int slot, int kof) {
        uint32_t base = sb + slot * 16384;
        cp_async16(base + sAoff,        Ag + kof);
        cp_async16(base + sAoff + 4096, Ag + kof + (size_t)64 * K3);
        cp_async16(base + sAoff + 8192, Bg + kof);
        cp_async16(base + sAoff + 12288,Bg + kof + (size_t)64 * K3);
    };

    float acc[2][8][4];
#pragma unroll
    for (int mi = 0; mi < 2; ++mi)
#pragma unroll
        for (int ni = 0; ni < 8; ++ni)
#pragma unroll
            for (int q = 0; q < 4; ++q) acc[mi][ni][q] = 0.0f;

    issue(0, 0);  CP_COMMIT();
    issue(1, 32); CP_COMMIT();
    issue(2, 64); CP_COMMIT();

    const int NIT = K3 / 32;   // 16
    for (int it = 0; it < NIT; ++it) {
        CP_WAIT(2);
        __syncthreads();
        uint32_t stg = sb + (it & 3) * 16384;
        MMA_STAGE(stg);
        if (it + 3 < NIT) issue((it + 3) & 3, (it + 3) * 32);
        CP_COMMIT();
    }

    // Epilogue with D*u feedthrough
#pragma unroll
    for (int mi = 0; mi < 2; ++mi) {
        int row0 = m0 + mBase + mi * 16 + g;
#pragma unroll
        for (int ni = 0; ni < 8; ++ni) {
            int col = n0 + nBase + ni * 8 + 2 * tig;
            float d0 = Dvec[col], d1 = Dvec[col + 1];
            float2 u0 = *(const float2*)(U + (size_t)row0 * HDIM + col);
            float2 u1 = *(const float2*)(U + (size_t)(row0 + 8) * HDIM + col);
            float2 v0 = make_float2(fmaf(d0, u0.x, acc[mi][ni][0]),
                                    fmaf(d1, u0.y, acc[mi][ni][1]));
            float2 v1 = make_float2(fmaf(d0, u1.x, acc[mi][ni][2]),
                                    fmaf(d1, u1.y, acc[mi][ni][3]));
            *(float2*)(C + (size_t)row0 * N3 + col) = v0;
            *(float2*)(C + (size_t)(row0 + 8) * N3 + col) = v1;
        }
    }
}

// ---------------------------------------------------------------------------
extern "C" void kernel_launch(void* const* d_in, const int* in_sizes, int n_in,
                              void* d_out, int out_size)
{
    const float* u   = (const float*)d_in[0];
    const float* Lre = (const float*)d_in[1];
    const float* Lim = (const float*)d_in[2];
    const float* Bp  = (const float*)d_in[3];
    const float* Cp  = (const float*)d_in[4];
    const float* Dv  = (const float*)d_in[5];
    const float* lst = (const float*)d_in[6];
    float* out = (float*)d_out;

    cudaFuncSetAttribute(s5_gemm1_scan,
                         cudaFuncAttributeMaxDynamicSharedMemorySize, G1_SMEM);
    cudaFuncSetAttribute(s5_gemm3,
                         cudaFuncAttributeMaxDynamicSharedMemorySize, G3_SMEM);

    // 1. discretize + pack fp16 weights + power tables;  u->fp16 + flag clear
    s5_setup_kernel<<<PDIM, HDIM>>>(Lre, Lim, Bp, Cp, lst);
    s5_u2h_kernel<<<(MROWS * HDIM) / 2048, 256>>>(u);

    // 2. Bu GEMM + fused full scan (lookback) -> final states fp16 (g_S16)
    s5_gemm1_scan<<<dim3(N1 / 128, MROWS / 128), 256, G1_SMEM>>>();

    // 3. y = states16 @ Wc16^T + D*u
    s5_gemm3<<<dim3(N3 / 128, MROWS / 128), 256, G3_SMEM>>>(out, Dv, u);
}

// round 13
// speedup vs baseline: 1.3343x; 1.2702x over previous
#include <cuda_runtime.h>
#include <cuda_fp16.h>
#include <math.h>
#include <stdint.h>

// Problem dims
#define BSZ   16
#define LSEQ  1024
#define HDIM  256
#define PDIM  256
#define MROWS (BSZ*LSEQ)     // 16384
#define N1    (2*PDIM)       // 512  (interleaved re/im: col 2p, 2p+1)
#define K1    HDIM           // 256
#define N3    HDIM           // 256
#define K3    (2*PDIM)       // 512
#define CHUNK 128            // == GEMM tile M
#define NCH   (LSEQ/CHUNK)   // 8
#define NMCH  (MROWS/CHUNK)  // 128 m-chunks

// Scratch (static device memory; no allocations allowed)
__device__ __align__(128) __half g_S16[(size_t)MROWS * N1];  // 16 MB: final states fp16
__device__ __align__(128) __half g_u16[(size_t)MROWS * HDIM];// 8 MB: u in fp16
__device__ __align__(128) __half g_Wb16[N1 * K1];            // (512,256) N-major, K-contig
__device__ __align__(128) __half g_Wc16[N3 * K3];            // (256,512) N-major, K-contig
__device__ float g_lam_re[PDIM], g_lam_im[PDIM];
__device__ float g_lam32_re[PDIM], g_lam32_im[PDIM];         // lam^32   (fp64-exact)
__device__ float g_pow32_re[4][PDIM], g_pow32_im[4][PDIM];   // lam^(32q)
__device__ float g_powT_re[NCH][PDIM], g_powT_im[NCH][PDIM]; // lam^(128j)
__device__ float g_inv_scl[PDIM];
__device__ __align__(128) float    g_car[BSZ * NCH * PDIM * 2]; // chunk aggregates
__device__ __align__(128) unsigned g_flag[BSZ * NCH * PDIM];    // per-p publish flags
__device__ __align__(128) unsigned g_done[NMCH];                // per-m-chunk S16-ready count

// ---------------------------------------------------------------------------
// helpers
// ---------------------------------------------------------------------------
__device__ __forceinline__ uint32_t smem_u32(const void* p) {
    uint32_t a;
    asm("{ .reg .u64 t; cvta.to.shared.u64 t, %1; cvt.u32.u64 %0, t; }" : "=r"(a) : "l"(p));
    return a;
}
__device__ __forceinline__ uint32_t f2h2(float a, float b) {   // lo=a, hi=b
    uint32_t r;
    asm("cvt.rn.f16x2.f32 %0, %1, %2;" : "=r"(r) : "f"(b), "f"(a));
    return r;
}
__device__ __forceinline__ void cp_async16(uint32_t saddr, const void* gaddr) {
    asm volatile("cp.async.cg.shared.global [%0], [%1], 16;" :: "r"(saddr), "l"(gaddr));
}
#define CP_COMMIT() asm volatile("cp.async.commit_group;" ::: "memory")
#define CP_WAIT(n)  asm volatile("cp.async.wait_group %0;" :: "n"(n) : "memory")

__device__ __forceinline__ void st_release_u32(unsigned* p, unsigned v) {
    asm volatile("st.release.gpu.global.u32 [%0], %1;" :: "l"(p), "r"(v) : "memory");
}
__device__ __forceinline__ unsigned ld_acquire_u32(const unsigned* p) {
    unsigned v;
    asm volatile("ld.acquire.gpu.global.u32 %0, [%1];" : "=r"(v) : "l"(p) : "memory");
    return v;
}
__device__ __forceinline__ void red_release_add(unsigned* p, unsigned v) {
    asm volatile("red.release.gpu.global.add.u32 [%0], %1;" :: "l"(p), "r"(v) : "memory");
}
__device__ __forceinline__ float2 ld_relaxed_f2(const float* p) {
    float2 v;
    asm volatile("ld.relaxed.gpu.global.v2.f32 {%0,%1}, [%2];"
                 : "=f"(v.x), "=f"(v.y) : "l"(p) : "memory");
    return v;
}

__device__ __forceinline__ void ldsm4(uint32_t& r0, uint32_t& r1, uint32_t& r2,
                                      uint32_t& r3, uint32_t addr) {
    asm volatile("ldmatrix.sync.aligned.m8n8.x4.shared.b16 {%0,%1,%2,%3}, [%4];"
                 : "=r"(r0), "=r"(r1), "=r"(r2), "=r"(r3) : "r"(addr));
}
__device__ __forceinline__ void mma16816(float c[4], const uint32_t a[4],
                                         uint32_t b0, uint32_t b1) {
    asm volatile(
        "mma.sync.aligned.m16n8k16.row.col.f32.f16.f16.f32 "
        "{%0,%1,%2,%3}, {%4,%5,%6,%7}, {%8,%9}, {%0,%1,%2,%3};"
        : "+f"(c[0]), "+f"(c[1]), "+f"(c[2]), "+f"(c[3])
        : "r"(a[0]), "r"(a[1]), "r"(a[2]), "r"(a[3]), "r"(b0), "r"(b1));
}

// MMA block on one 32-k stage (fragment maps validated rounds 5-12).
#define MMA_STAGE(stgAddr)                                                    \
    do {                                                                      \
        _Pragma("unroll")                                                     \
        for (int ks = 0; ks < 2; ++ks) {                                      \
            const int cbase = ks * 2;                                         \
            uint32_t af[2][4];                                                \
            _Pragma("unroll")                                                 \
            for (int mi = 0; mi < 2; ++mi) {                                  \
                int ml = mBase + mi * 16 + (lane & 15);                       \
                int ci = (cbase + (lane >> 4)) ^ ((ml >> 1) & 3);             \
                ldsm4(af[mi][0], af[mi][1], af[mi][2], af[mi][3],             \
                      (stgAddr) + ml * 64 + ci * 16);                         \
            }                                                                 \
            uint32_t bf[4][4];                                                \
            _Pragma("unroll")                                                 \
            for (int nj = 0; nj < 4; ++nj) {                                  \
                int nl = nBase + nj * 16 + ((lane >> 4) & 1) * 8 + (lane & 7);\
                int ci = (cbase + ((lane >> 3) & 1)) ^ ((nl >> 1) & 3);       \
                ldsm4(bf[nj][0], bf[nj][1], bf[nj][2], bf[nj][3],             \
                      (stgAddr) + 8192 + nl * 64 + ci * 16);                  \
            }                                                                 \
            _Pragma("unroll")                                                 \
            for (int mi = 0; mi < 2; ++mi)                                    \
                _Pragma("unroll")                                             \
                for (int nj = 0; nj < 4; ++nj) {                              \
                    mma16816(acc[mi][nj * 2 + 0], af[mi], bf[nj][0], bf[nj][1]);\
                    mma16816(acc[mi][nj * 2 + 1], af[mi], bf[nj][2], bf[nj][3]);\
                }                                                             \
        }                                                                     \
    } while (0)

// ---------------------------------------------------------------------------
// u -> fp16 conversion + flag/done clear (one-shot).  grid = 2048, block 256.
// ---------------------------------------------------------------------------
__global__ void s5_u2h_kernel(const float* __restrict__ u)
{
    size_t i = ((size_t)blockIdx.x * 256 + threadIdx.x) * 8;
    float4 a = *(const float4*)(u + i);
    float4 b = *(const float4*)(u + i + 4);
    *(uint4*)(g_u16 + i) = make_uint4(f2h2(a.x, a.y), f2h2(a.z, a.w),
                                      f2h2(b.x, b.y), f2h2(b.z, b.w));
    if (blockIdx.x < 32) {   // clear 32768 flags (8192 uint4)
        ((uint4*)g_flag)[blockIdx.x * 256 + threadIdx.x] =
            make_uint4(0u, 0u, 0u, 0u);
    }
    if (blockIdx.x == 32 && threadIdx.x < NMCH) g_done[threadIdx.x] = 0u;
}

// ---------------------------------------------------------------------------
// Setup: discretization, fp16 weight packing, fp64-exact power tables,
// per-p power-of-2 prescale of Wb.  grid = PDIM, block = HDIM.
// ---------------------------------------------------------------------------
__global__ void s5_setup_kernel(const float* __restrict__ Lre,
                                const float* __restrict__ Lim,
                                const float* __restrict__ Bp,
                                const float* __restrict__ Cp,
                                const float* __restrict__ lstep)
{
    int p = blockIdx.x;
    int h = threadIdx.x;

    double lre = (double)Lre[p], lim = (double)Lim[p];
    double delta = exp((double)lstep[p]);
    double a = lre * delta, b = lim * delta;
    double ea = exp(a);
    double lam_r = ea * cos(b);
    double lam_i = ea * sin(b);
    double d2 = lre * lre + lim * lim;
    double nr = lam_r - 1.0, ni = lam_i;
    double cr = (nr * lre + ni * lim) / d2;
    double ci = (ni * lre - nr * lim) / d2;

    int e;
    frexp(sqrt(cr * cr + ci * ci), &e);
    double scl = ldexp(1.0, -e);
    cr *= scl; ci *= scl;

    float br = Bp[((size_t)p * HDIM + h) * 2 + 0];
    float bi = Bp[((size_t)p * HDIM + h) * 2 + 1];
    g_Wb16[(size_t)(2 * p) * K1 + h]     = __float2half((float)(cr * br - ci * bi));
    g_Wb16[(size_t)(2 * p + 1) * K1 + h] = __float2half((float)(cr * bi + ci * br));

    float ccr = Cp[((size_t)h * PDIM + p) * 2 + 0];
    float cci = Cp[((size_t)h * PDIM + p) * 2 + 1];
    g_Wc16[(size_t)h * K3 + 2 * p]     = __float2half( 2.0f * ccr);
    g_Wc16[(size_t)h * K3 + 2 * p + 1] = __float2half(-2.0f * cci);

    if (h == 0) {
        g_lam_re[p] = (float)lam_r;
        g_lam_im[p] = (float)lam_i;
        g_inv_scl[p] = (float)ldexp(1.0, e);
        double a32 = a * 32.0, b32 = b * 32.0;
        double e32 = exp(a32);
        g_lam32_re[p] = (float)(e32 * cos(b32));
        g_lam32_im[p] = (float)(e32 * sin(b32));
    }
    if (h < 4) {   // lam^(32h)
        double aq = a * 32.0 * h, bq = b * 32.0 * h;
        double eq = exp(aq);
        g_pow32_re[h][p] = (float)(eq * cos(bq));
        g_pow32_im[h][p] = (float)(eq * sin(bq));
    }
    if (h < NCH) { // lam^(128h)
        double aT = a * (double)(CHUNK * h), bT = b * (double)(CHUNK * h);
        double eaT = exp(aT);
        g_powT_re[h][p] = (float)(eaT * cos(bT));
        g_powT_im[h][p] = (float)(eaT * sin(bT));
    }
}

// ---------------------------------------------------------------------------
// FUSED kernel: 768 blocks, interleaved roles per m-chunk (6 blocks each):
//   r = bid % 6:  r<4 -> GEMM1+scan tile (n-tile r);  r>=4 -> GEMM3 tile.
// GEMM1 blocks publish S16 readiness per m-chunk (release-add);
// GEMM3 blocks acquire-spin for count==4, then run.  All waited-on blocks
// have strictly lower bid -> deadlock-free under monotonic scheduling.
// ---------------------------------------------------------------------------
#define FU_SMEM 70656

__global__ void __launch_bounds__(256)
s5_fused(float* __restrict__ C,
         const float* __restrict__ Dvec,
         const float* __restrict__ U)
{
    extern __shared__ char sm[];
    uint32_t sb = smem_u32(sm);

    const int bid = blockIdx.x;
    const int mchunk = bid / 6;
    const int role = bid % 6;

    const int t = threadIdx.x;
    const int lane = t & 31, w = t >> 5;
    const int g = lane >> 2, tig = lane & 3;
    const int mBase = (w & 3) * 32;
    const int nBase = (w >> 2) * 64;
    const int m0 = mchunk * 128;

    const int r0 = t >> 2, c0 = t & 3;
    const uint32_t sAoff = r0 * 64 + (((uint32_t)(c0 ^ ((r0 >> 1) & 3))) << 4);

    float acc[2][8][4];
#pragma unroll
    for (int mi = 0; mi < 2; ++mi)
#pragma unroll
        for (int ni = 0; ni < 8; ++ni)
#pragma unroll
            for (int q = 0; q < 4; ++q) acc[mi][ni][q] = 0.0f;

    if (role < 4) {
        // =================== GEMM1 + fused scan ===================
        const int n0 = role * 128;
        const int bIdx = m0 >> 10, cIdx = (m0 >> 7) & (NCH - 1);
        const __half* Ag = g_u16 + (size_t)(m0 + r0) * K1 + c0 * 8;
        const __half* Bg = g_Wb16 + (size_t)(n0 + r0) * K1 + c0 * 8;

        auto issue = [&](int slot, int kof) {
            uint32_t base = sb + slot * 16384;
            cp_async16(base + sAoff,        Ag + kof);
            cp_async16(base + sAoff + 4096, Ag + kof + (size_t)64 * K1);
            cp_async16(base + sAoff + 8192, Bg + kof);
            cp_async16(base + sAoff + 12288,Bg + kof + (size_t)64 * K1);
        };

        issue(0, 0);  CP_COMMIT();
        issue(1, 32); CP_COMMIT();
        issue(2, 64); CP_COMMIT();

        const int NIT = K1 / 32;   // 8
        for (int it = 0; it < NIT; ++it) {
            CP_WAIT(2);
            __syncthreads();
            uint32_t stg = sb + (it & 3) * 16384;
            MMA_STAGE(stg);
            if (it + 3 < NIT) issue((it + 3) & 3, (it + 3) * 32);
            CP_COMMIT();
        }
        CP_WAIT(0);
        __syncthreads();   // pipeline smem dead; reuse as Stile

        float* Stile = (float*)sm;              // 128 x 130
        float* carrR = (float*)(sm + 66560);    // [4][64]  (later: E_chunk)
        float* carrI = carrR + 256;
        float* prefR = carrI + 256;             // [4][64]
        float* prefI = prefR + 256;

        // 1. accs -> Stile
#pragma unroll
        for (int mi = 0; mi < 2; ++mi) {
            int row = mBase + mi * 16 + g;
#pragma unroll
            for (int ni = 0; ni < 8; ++ni) {
                int col = nBase + ni * 8 + 2 * tig;
                *(float2*)(Stile + row * 130 + col) =
                    make_float2(acc[mi][ni][0], acc[mi][ni][1]);
                *(float2*)(Stile + (row + 8) * 130 + col) =
                    make_float2(acc[mi][ni][2], acc[mi][ni][3]);
            }
        }
        __syncthreads();

        // 2. segment-local scan (zero init), 4 segs x 64 complex cols
        const int pl = t & 63, seg = t >> 6;
        const int pg = (n0 >> 1) + pl;
        const float lr = g_lam_re[pg], li = g_lam_im[pg];
        {
            float yr = 0.f, yi = 0.f;
            float* colp = Stile + 2 * pl;
#pragma unroll 4
            for (int tt = 0; tt < 32; ++tt) {
                int row = seg * 32 + tt;
                float2 s = *(float2*)(colp + row * 130);
                float nyr = fmaf(lr, yr, fmaf(-li, yi, s.x));
                float nyi = fmaf(lr, yi, fmaf( li, yr, s.y));
                yr = nyr; yi = nyi;
                *(float2*)(colp + row * 130) = make_float2(yr, yi);
            }
            carrR[seg * 64 + pl] = yr;
            carrI[seg * 64 + pl] = yi;
        }
        __syncthreads();

        // 3. seg-carry combine -> chunk aggregate; publish; lookback.
        if (t < 64) {
            int pg2 = (n0 >> 1) + t;
            float l32r = g_lam32_re[pg2], l32i = g_lam32_im[pg2];
            float Pr = 0.f, Pi = 0.f;
            float sp[4][2];
#pragma unroll
            for (int q = 0; q < 4; ++q) {
                sp[q][0] = Pr; sp[q][1] = Pi;
                float cr = carrR[q * 64 + t], ci = carrI[q * 64 + t];
                float nPr = fmaf(l32r, Pr, fmaf(-l32i, Pi, cr));
                float nPi = fmaf(l32r, Pi, fmaf( l32i, Pr, ci));
                Pr = nPr; Pi = nPi;
            }
            size_t ci0 = (size_t)(bIdx * NCH + cIdx) * PDIM + pg2;
            *(float2*)(g_car + 2 * ci0) = make_float2(Pr, Pi);
            st_release_u32(g_flag + ci0, 1u);

            float Ecr = 0.f, Eci = 0.f;
            for (int j = 0; j < cIdx; ++j) {
                int d = cIdx - 1 - j;
                size_t fj = (size_t)(bIdx * NCH + j) * PDIM + pg2;
                while (ld_acquire_u32(g_flag + fj) == 0) { }
                float2 cv = ld_relaxed_f2(g_car + 2 * fj);
                float pr = g_powT_re[d][pg2], pi = g_powT_im[d][pg2];
                Ecr = fmaf(pr, cv.x, fmaf(-pi, cv.y, Ecr));
                Eci = fmaf(pr, cv.y, fmaf( pi, cv.x, Eci));
            }
#pragma unroll
            for (int q = 0; q < 4; ++q) {
                prefR[q * 64 + t] = sp[q][0];
                prefI[q * 64 + t] = sp[q][1];
            }
            carrR[t] = Ecr;
            carrI[t] = Eci;
        }
        __syncthreads();

        // 4. total prefix apply + fp16 convert, write final states to g_S16
        {
            float Ecr = carrR[pl], Eci = carrI[pl];
            float p32r = g_pow32_re[seg][pg], p32i = g_pow32_im[seg][pg];
            float Er = prefR[seg * 64 + pl] + p32r * Ecr - p32i * Eci;
            float Ei = prefI[seg * 64 + pl] + p32r * Eci + p32i * Ecr;
            float inv = g_inv_scl[pg];
            float wr = lr, wi = li;
            float* colp = Stile + 2 * pl;
            __half2* op = (__half2*)g_S16 + (size_t)m0 * PDIM + pg;
#pragma unroll 4
            for (int tt = 0; tt < 32; ++tt) {
                int row = seg * 32 + tt;
                float2 s = *(float2*)(colp + row * 130);
                float xr = fmaf(wr, Er, fmaf(-wi, Ei, s.x));
                float xi = fmaf(wr, Ei, fmaf( wi, Er, s.y));
                op[(size_t)row * PDIM] = __floats2half2_rn(xr * inv, xi * inv);
                float nwr = fmaf(wr, lr, -wi * li);
                float nwi = fmaf(wr, li,  wi * lr);
                wr = nwr; wi = nwi;
            }
        }
        // publish S16-chunk readiness
        __threadfence();
        __syncthreads();
        if (t == 0) red_release_add(g_done + mchunk, 1u);

    } else {
        // =================== GEMM3 ===================
        const int n0 = (role - 4) * 128;
        // wait for this m-chunk's states
        if (t == 0) {
            while (ld_acquire_u32(g_done + mchunk) != 4u) { }
        }
        __syncthreads();

        const __half* Ag = g_S16 + (size_t)(m0 + r0) * K3 + c0 * 8;
        const __half* Bg = g_Wc16 + (size_t)(n0 + r0) * K3 + c0 * 8;

        auto issue = [&](int slot, int kof) {
            uint32_t base = sb + slot * 16384;
            cp_async16(base + sAoff,        Ag + kof);
            cp_async16(base + sAoff + 4096, Ag + kof + (size_t)64 * K3);
            cp_async16(base + sAoff + 8192, Bg + kof);
            cp_async16(base + sAoff + 12288,Bg + kof + (size_t)64 * K3);
        };

        issue(0, 0);  CP_COMMIT();
        issue(1, 32); CP_COMMIT();
        issue(2, 64); CP_COMMIT();

        const int NIT = K3 / 32;   // 16
        for (int it = 0; it < NIT; ++it) {
            CP_WAIT(2);
            __syncthreads();
            uint32_t stg = sb + (it & 3) * 16384;
            MMA_STAGE(stg);
            if (it + 3 < NIT) issue((it + 3) & 3, (it + 3) * 32);
            CP_COMMIT();
        }

        // Epilogue with D*u feedthrough
#pragma unroll
        for (int mi = 0; mi < 2; ++mi) {
            int row0 = m0 + mBase + mi * 16 + g;
#pragma unroll
            for (int ni = 0; ni < 8; ++ni) {
                int col = n0 + nBase + ni * 8 + 2 * tig;
                float d0 = Dvec[col], d1 = Dvec[col + 1];
                float2 u0 = *(const float2*)(U + (size_t)row0 * HDIM + col);
                float2 u1 = *(const float2*)(U + (size_t)(row0 + 8) * HDIM + col);
                float2 v0 = make_float2(fmaf(d0, u0.x, acc[mi][ni][0]),
                                        fmaf(d1, u0.y, acc[mi][ni][1]));
                float2 v1 = make_float2(fmaf(d0, u1.x, acc[mi][ni][2]),
                                        fmaf(d1, u1.y, acc[mi][ni][3]));
                *(float2*)(C + (size_t)row0 * N3 + col) = v0;
                *(float2*)(C + (size_t)(row0 + 8) * N3 + col) = v1;
            }
        }
    }
}

// ---------------------------------------------------------------------------
extern "C" void kernel_launch(void* const* d_in, const int* in_sizes, int n_in,
                              void* d_out, int out_size)
{
    const float* u   = (const float*)d_in[0];
    const float* Lre = (const float*)d_in[1];
    const float* Lim = (const float*)d_in[2];
    const float* Bp  = (const float*)d_in[3];
    const float* Cp  = (const float*)d_in[4];
    const float* Dv  = (const float*)d_in[5];
    const float* lst = (const float*)d_in[6];
    float* out = (float*)d_out;

    cudaFuncSetAttribute(s5_fused,
                         cudaFuncAttributeMaxDynamicSharedMemorySize, FU_SMEM);

    // 1. discretize + pack fp16 weights + power tables;  u->fp16 + flag clear
    s5_setup_kernel<<<PDIM, HDIM>>>(Lre, Lim, Bp, Cp, lst);
    s5_u2h_kernel<<<(MROWS * HDIM) / 2048, 256>>>(u);

    // 2. fused: Bu GEMM + full scan + output GEMM (dataflow-synchronized)
    s5_fused<<<NMCH * 6, 256, FU_SMEM>>>(out, Dv, u);
}

// round 14
// speedup vs baseline: 1.5947x; 1.1951x over previous
#include <cuda_runtime.h>
#include <cuda_fp16.h>
#include <math.h>
#include <stdint.h>

// Problem dims
#define BSZ   16
#define LSEQ  1024
#define HDIM  256
#define PDIM  256
#define MROWS (BSZ*LSEQ)     // 16384
#define N1    (2*PDIM)       // 512  (interleaved re/im: col 2p, 2p+1)
#define K1    HDIM           // 256
#define N3    HDIM           // 256
#define K3    (2*PDIM)       // 512
#define CHUNK 128            // == GEMM tile M
#define NCH   (LSEQ/CHUNK)   // 8
#define NMCH  (MROWS/CHUNK)  // 128 m-chunks

// Scratch (static device memory; no allocations allowed)
__device__ __align__(128) __half g_S16[(size_t)MROWS * N1];  // 16 MB: final states fp16
__device__ __align__(128) __half g_u16[(size_t)MROWS * HDIM];// 8 MB: u in fp16
__device__ __align__(128) __half g_Wb16[N1 * K1];            // (512,256) N-major, K-contig
__device__ __align__(128) __half g_Wc16[N3 * K3];            // (256,512) N-major, K-contig
__device__ float2 g_coef[PDIM];                              // scaled (Lambda_bar-1)/Lambda
__device__ float g_lam_re[PDIM], g_lam_im[PDIM];
__device__ float g_lam32_re[PDIM], g_lam32_im[PDIM];         // lam^32
__device__ float g_pow32_re[4][PDIM], g_pow32_im[4][PDIM];   // lam^(32q)
__device__ float g_powT_re[NCH][PDIM], g_powT_im[NCH][PDIM]; // lam^(128j)
__device__ float g_inv_scl[PDIM];
__device__ __align__(128) float    g_car[BSZ * NCH * PDIM * 2]; // chunk aggregates
__device__ __align__(128) unsigned g_flag[BSZ * NCH * PDIM];    // per-p publish flags
__device__ __align__(128) unsigned g_done[NMCH];                // per-m-chunk S16-ready count

// ---------------------------------------------------------------------------
// helpers
// ---------------------------------------------------------------------------
__device__ __forceinline__ uint32_t smem_u32(const void* p) {
    uint32_t a;
    asm("{ .reg .u64 t; cvta.to.shared.u64 t, %1; cvt.u32.u64 %0, t; }" : "=r"(a) : "l"(p));
    return a;
}
__device__ __forceinline__ uint32_t f2h2(float a, float b) {   // lo=a, hi=b
    uint32_t r;
    asm("cvt.rn.f16x2.f32 %0, %1, %2;" : "=r"(r) : "f"(b), "f"(a));
    return r;
}
__device__ __forceinline__ void cp_async16(uint32_t saddr, const void* gaddr) {
    asm volatile("cp.async.cg.shared.global [%0], [%1], 16;" :: "r"(saddr), "l"(gaddr));
}
#define CP_COMMIT() asm volatile("cp.async.commit_group;" ::: "memory")
#define CP_WAIT(n)  asm volatile("cp.async.wait_group %0;" :: "n"(n) : "memory")

__device__ __forceinline__ void st_release_u32(unsigned* p, unsigned v) {
    asm volatile("st.release.gpu.global.u32 [%0], %1;" :: "l"(p), "r"(v) : "memory");
}
__device__ __forceinline__ unsigned ld_acquire_u32(const unsigned* p) {
    unsigned v;
    asm volatile("ld.acquire.gpu.global.u32 %0, [%1];" : "=r"(v) : "l"(p) : "memory");
    return v;
}
__device__ __forceinline__ void red_release_add(unsigned* p, unsigned v) {
    asm volatile("red.release.gpu.global.add.u32 [%0], %1;" :: "l"(p), "r"(v) : "memory");
}
__device__ __forceinline__ float2 ld_relaxed_f2(const float* p) {
    float2 v;
    asm volatile("ld.relaxed.gpu.global.v2.f32 {%0,%1}, [%2];"
                 : "=f"(v.x), "=f"(v.y) : "l"(p) : "memory");
    return v;
}

__device__ __forceinline__ void ldsm4(uint32_t& r0, uint32_t& r1, uint32_t& r2,
                                      uint32_t& r3, uint32_t addr) {
    asm volatile("ldmatrix.sync.aligned.m8n8.x4.shared.b16 {%0,%1,%2,%3}, [%4];"
                 : "=r"(r0), "=r"(r1), "=r"(r2), "=r"(r3) : "r"(addr));
}
__device__ __forceinline__ void mma16816(float c[4], const uint32_t a[4],
                                         uint32_t b0, uint32_t b1) {
    asm volatile(
        "mma.sync.aligned.m16n8k16.row.col.f32.f16.f16.f32 "
        "{%0,%1,%2,%3}, {%4,%5,%6,%7}, {%8,%9}, {%0,%1,%2,%3};"
        : "+f"(c[0]), "+f"(c[1]), "+f"(c[2]), "+f"(c[3])
        : "r"(a[0]), "r"(a[1]), "r"(a[2]), "r"(a[3]), "r"(b0), "r"(b1));
}

// MMA block on one 32-k stage (fragment maps validated rounds 5-13).
#define MMA_STAGE(stgAddr)                                                    \
    do {                                                                      \
        _Pragma("unroll")                                                     \
        for (int ks = 0; ks < 2; ++ks) {                                      \
            const int cbase = ks * 2;                                         \
            uint32_t af[2][4];                                                \
            _Pragma("unroll")                                                 \
            for (int mi = 0; mi < 2; ++mi) {                                  \
                int ml = mBase + mi * 16 + (lane & 15);                       \
                int ci = (cbase + (lane >> 4)) ^ ((ml >> 1) & 3);             \
                ldsm4(af[mi][0], af[mi][1], af[mi][2], af[mi][3],             \
                      (stgAddr) + ml * 64 + ci * 16);                         \
            }                                                                 \
            uint32_t bf[4][4];                                                \
            _Pragma("unroll")                                                 \
            for (int nj = 0; nj < 4; ++nj) {                                  \
                int nl = nBase + nj * 16 + ((lane >> 4) & 1) * 8 + (lane & 7);\
                int ci = (cbase + ((lane >> 3) & 1)) ^ ((nl >> 1) & 3);       \
                ldsm4(bf[nj][0], bf[nj][1], bf[nj][2], bf[nj][3],             \
                      (stgAddr) + 8192 + nl * 64 + ci * 16);                  \
            }                                                                 \
            _Pragma("unroll")                                                 \
            for (int mi = 0; mi < 2; ++mi)                                    \
                _Pragma("unroll")                                             \
                for (int nj = 0; nj < 4; ++nj) {                              \
                    mma16816(acc[mi][nj * 2 + 0], af[mi], bf[nj][0], bf[nj][1]);\
                    mma16816(acc[mi][nj * 2 + 1], af[mi], bf[nj][2], bf[nj][3]);\
                }                                                             \
        }                                                                     \
    } while (0)

// ---------------------------------------------------------------------------
// Per-p constants.  ONLY 3 fp64 transcendentals per thread; all powers by
// fp64 complex squaring/multiplication (error ~1e-15, << fp32 targets).
// grid = 8, block = 32.
// ---------------------------------------------------------------------------
__global__ void s5_const_kernel(const float* __restrict__ Lre,
                                const float* __restrict__ Lim,
                                const float* __restrict__ lstep)
{
    int p = blockIdx.x * 32 + threadIdx.x;

    double lre = (double)Lre[p], lim = (double)Lim[p];
    double delta = exp((double)lstep[p]);            // transcendental 1
    double a = lre * delta, b = lim * delta;
    double ea = exp(a);                              // transcendental 2
    double sb_, cb_;
    sincos(b, &sb_, &cb_);                           // transcendental 3
    double lam_r = ea * cb_;
    double lam_i = ea * sb_;

    // coef = (lam - 1)/Lambda, power-of-2 prescaled
    double d2 = lre * lre + lim * lim;
    double nr = lam_r - 1.0, ni = lam_i;
    double cr = (nr * lre + ni * lim) / d2;
    double ci = (ni * lre - nr * lim) / d2;
    int e;
    frexp(sqrt(cr * cr + ci * ci), &e);
    double scl = ldexp(1.0, -e);
    g_coef[p] = make_float2((float)(cr * scl), (float)(ci * scl));
    g_inv_scl[p] = (float)ldexp(1.0, e);

    g_lam_re[p] = (float)lam_r;
    g_lam_im[p] = (float)lam_i;

    // lam^32 via 5 complex squarings (fp64)
    double xr = lam_r, xi = lam_i;
#pragma unroll
    for (int i = 0; i < 5; ++i) {
        double tr = xr * xr - xi * xi;
        double ti = 2.0 * xr * xi;
        xr = tr; xi = ti;
    }
    g_lam32_re[p] = (float)xr;
    g_lam32_im[p] = (float)xi;

    // pow32[q] = lam^(32q), q = 0..3
    double p2r = xr * xr - xi * xi, p2i = 2.0 * xr * xi;          // lam^64
    double p3r = p2r * xr - p2i * xi, p3i = p2r * xi + p2i * xr;  // lam^96
    g_pow32_re[0][p] = 1.0f;        g_pow32_im[0][p] = 0.0f;
    g_pow32_re[1][p] = (float)xr;   g_pow32_im[1][p] = (float)xi;
    g_pow32_re[2][p] = (float)p2r;  g_pow32_im[2][p] = (float)p2i;
    g_pow32_re[3][p] = (float)p3r;  g_pow32_im[3][p] = (float)p3i;

    // lam^128 = (lam^64)^2;  powT[j] = lam^(128j) by iterated multiply
    double l128r = p2r * p2r - p2i * p2i;
    double l128i = 2.0 * p2r * p2i;
    double tr = 1.0, ti = 0.0;
#pragma unroll
    for (int j = 0; j < NCH; ++j) {
        g_powT_re[j][p] = (float)tr;
        g_powT_im[j][p] = (float)ti;
        double ntr = tr * l128r - ti * l128i;
        double nti = tr * l128i + ti * l128r;
        tr = ntr; ti = nti;
    }
}

// ---------------------------------------------------------------------------
// fp32 weight packing.  grid = PDIM, block = HDIM.
// ---------------------------------------------------------------------------
__global__ void s5_pack_kernel(const float* __restrict__ Bp,
                               const float* __restrict__ Cp)
{
    int p = blockIdx.x;
    int h = threadIdx.x;
    float2 cf = g_coef[p];

    float br = Bp[((size_t)p * HDIM + h) * 2 + 0];
    float bi = Bp[((size_t)p * HDIM + h) * 2 + 1];
    g_Wb16[(size_t)(2 * p) * K1 + h]     = __float2half(cf.x * br - cf.y * bi);
    g_Wb16[(size_t)(2 * p + 1) * K1 + h] = __float2half(cf.x * bi + cf.y * br);

    float ccr = Cp[((size_t)h * PDIM + p) * 2 + 0];
    float cci = Cp[((size_t)h * PDIM + p) * 2 + 1];
    g_Wc16[(size_t)h * K3 + 2 * p]     = __float2half( 2.0f * ccr);
    g_Wc16[(size_t)h * K3 + 2 * p + 1] = __float2half(-2.0f * cci);
}

// ---------------------------------------------------------------------------
// u -> fp16 conversion + flag/done clear (one-shot).  grid = 2048, block 256.
// ---------------------------------------------------------------------------
__global__ void s5_u2h_kernel(const float* __restrict__ u)
{
    size_t i = ((size_t)blockIdx.x * 256 + threadIdx.x) * 8;
    float4 a = *(const float4*)(u + i);
    float4 b = *(const float4*)(u + i + 4);
    *(uint4*)(g_u16 + i) = make_uint4(f2h2(a.x, a.y), f2h2(a.z, a.w),
                                      f2h2(b.x, b.y), f2h2(b.z, b.w));
    if (blockIdx.x < 32) {   // clear 32768 flags (8192 uint4)
        ((uint4*)g_flag)[blockIdx.x * 256 + threadIdx.x] =
            make_uint4(0u, 0u, 0u, 0u);
    }
    if (blockIdx.x == 32 && threadIdx.x < NMCH) g_done[threadIdx.x] = 0u;
}

// ---------------------------------------------------------------------------
// FUSED kernel: 768 blocks, interleaved roles per m-chunk (6 blocks each):
//   r = bid % 6:  r<4 -> GEMM1+scan tile (n-tile r);  r>=4 -> GEMM3 tile.
// GEMM1 blocks publish S16 readiness per m-chunk (release-add);
// GEMM3 blocks acquire-spin for count==4, then run.  All waited-on blocks
// have strictly lower bid -> deadlock-free under monotonic scheduling.
// ---------------------------------------------------------------------------
#define FU_SMEM 70656

__global__ void __launch_bounds__(256)
s5_fused(float* __restrict__ C,
         const float* __restrict__ Dvec,
         const float* __restrict__ U)
{
    extern __shared__ char sm[];
    uint32_t sb = smem_u32(sm);

    const int bid = blockIdx.x;
    const int mchunk = bid / 6;
    const int role = bid % 6;

    const int t = threadIdx.x;
    const int lane = t & 31, w = t >> 5;
    const int g = lane >> 2, tig = lane & 3;
    const int mBase = (w & 3) * 32;
    const int nBase = (w >> 2) * 64;
    const int m0 = mchunk * 128;

    const int r0 = t >> 2, c0 = t & 3;
    const uint32_t sAoff = r0 * 64 + (((uint32_t)(c0 ^ ((r0 >> 1) & 3))) << 4);

    float acc[2][8][4];
#pragma unroll
    for (int mi = 0; mi < 2; ++mi)
#pragma unroll
        for (int ni = 0; ni < 8; ++ni)
#pragma unroll
            for (int q = 0; q < 4; ++q) acc[mi][ni][q] = 0.0f;

    if (role < 4) {
        // =================== GEMM1 + fused scan ===================
        const int n0 = role * 128;
        const int bIdx = m0 >> 10, cIdx = (m0 >> 7) & (NCH - 1);
        const __half* Ag = g_u16 + (size_t)(m0 + r0) * K1 + c0 * 8;
        const __half* Bg = g_Wb16 + (size_t)(n0 + r0) * K1 + c0 * 8;

        auto issue = [&](int slot, int kof) {
            uint32_t base = sb + slot * 16384;
            cp_async16(base + sAoff,        Ag + kof);
            cp_async16(base + sAoff + 4096, Ag + kof + (size_t)64 * K1);
            cp_async16(base + sAoff + 8192, Bg + kof);
            cp_async16(base + sAoff + 12288,Bg + kof + (size_t)64 * K1);
        };

        issue(0, 0);  CP_COMMIT();
        issue(1, 32); CP_COMMIT();
        issue(2, 64); CP_COMMIT();

        const int NIT = K1 / 32;   // 8
        for (int it = 0; it < NIT; ++it) {
            CP_WAIT(2);
            __syncthreads();
            uint32_t stg = sb + (it & 3) * 16384;
            MMA_STAGE(stg);
            if (it + 3 < NIT) issue((it + 3) & 3, (it + 3) * 32);
            CP_COMMIT();
        }
        CP_WAIT(0);
        __syncthreads();   // pipeline smem dead; reuse as Stile

        float* Stile = (float*)sm;              // 128 x 130
        float* carrR = (float*)(sm + 66560);    // [4][64]  (later: E_chunk)
        float* carrI = carrR + 256;
        float* prefR = carrI + 256;             // [4][64]
        float* prefI = prefR + 256;

        // 1. accs -> Stile
#pragma unroll
        for (int mi = 0; mi < 2; ++mi) {
            int row = mBase + mi * 16 + g;
#pragma unroll
            for (int ni = 0; ni < 8; ++ni) {
                int col = nBase + ni * 8 + 2 * tig;
                *(float2*)(Stile + row * 130 + col) =
                    make_float2(acc[mi][ni][0], acc[mi][ni][1]);
                *(float2*)(Stile + (row + 8) * 130 + col) =
                    make_float2(acc[mi][ni][2], acc[mi][ni][3]);
            }
        }
        __syncthreads();

        // 2. segment-local scan (zero init), 4 segs x 64 complex cols
        const int pl = t & 63, seg = t >> 6;
        const int pg = (n0 >> 1) + pl;
        const float lr = g_lam_re[pg], li = g_lam_im[pg];
        {
            float yr = 0.f, yi = 0.f;
            float* colp = Stile + 2 * pl;
#pragma unroll 4
            for (int tt = 0; tt < 32; ++tt) {
                int row = seg * 32 + tt;
                float2 s = *(float2*)(colp + row * 130);
                float nyr = fmaf(lr, yr, fmaf(-li, yi, s.x));
                float nyi = fmaf(lr, yi, fmaf( li, yr, s.y));
                yr = nyr; yi = nyi;
                *(float2*)(colp + row * 130) = make_float2(yr, yi);
            }
            carrR[seg * 64 + pl] = yr;
            carrI[seg * 64 + pl] = yi;
        }
        __syncthreads();

        // 3. seg-carry combine -> chunk aggregate; publish; lookback.
        if (t < 64) {
            int pg2 = (n0 >> 1) + t;
            float l32r = g_lam32_re[pg2], l32i = g_lam32_im[pg2];
            float Pr = 0.f, Pi = 0.f;
            float sp[4][2];
#pragma unroll
            for (int q = 0; q < 4; ++q) {
                sp[q][0] = Pr; sp[q][1] = Pi;
                float cr = carrR[q * 64 + t], ci = carrI[q * 64 + t];
                float nPr = fmaf(l32r, Pr, fmaf(-l32i, Pi, cr));
                float nPi = fmaf(l32r, Pi, fmaf( l32i, Pr, ci));
                Pr = nPr; Pi = nPi;
            }
            size_t ci0 = (size_t)(bIdx * NCH + cIdx) * PDIM + pg2;
            *(float2*)(g_car + 2 * ci0) = make_float2(Pr, Pi);
            st_release_u32(g_flag + ci0, 1u);

            float Ecr = 0.f, Eci = 0.f;
            for (int j = 0; j < cIdx; ++j) {
                int d = cIdx - 1 - j;
                size_t fj = (size_t)(bIdx * NCH + j) * PDIM + pg2;
                while (ld_acquire_u32(g_flag + fj) == 0) { }
                float2 cv = ld_relaxed_f2(g_car + 2 * fj);
                float pr = g_powT_re[d][pg2], pi = g_powT_im[d][pg2];
                Ecr = fmaf(pr, cv.x, fmaf(-pi, cv.y, Ecr));
                Eci = fmaf(pr, cv.y, fmaf( pi, cv.x, Eci));
            }
#pragma unroll
            for (int q = 0; q < 4; ++q) {
                prefR[q * 64 + t] = sp[q][0];
                prefI[q * 64 + t] = sp[q][1];
            }
            carrR[t] = Ecr;
            carrI[t] = Eci;
        }
        __syncthreads();

        // 4. total prefix apply + fp16 convert, write final states to g_S16
        {
            float Ecr = carrR[pl], Eci = carrI[pl];
            float p32r = g_pow32_re[seg][pg], p32i = g_pow32_im[seg][pg];
            float Er = prefR[seg * 64 + pl] + p32r * Ecr - p32i * Eci;
            float Ei = prefI[seg * 64 + pl] + p32r * Eci + p32i * Ecr;
            float inv = g_inv_scl[pg];
            float wr = lr, wi = li;
            float* colp = Stile + 2 * pl;
            __half2* op = (__half2*)g_S16 + (size_t)m0 * PDIM + pg;
#pragma unroll 4
            for (int tt = 0; tt < 32; ++tt) {
                int row = seg * 32 + tt;
                float2 s = *(float2*)(colp + row * 130);
                float xr = fmaf(wr, Er, fmaf(-wi, Ei, s.x));
                float xi = fmaf(wr, Ei, fmaf( wi, Er, s.y));
                op[(size_t)row * PDIM] = __floats2half2_rn(xr * inv, xi * inv);
                float nwr = fmaf(wr, lr, -wi * li);
                float nwi = fmaf(wr, li,  wi * lr);
                wr = nwr; wi = nwi;
            }
        }
        // publish S16-chunk readiness
        __threadfence();
        __syncthreads();
        if (t == 0) red_release_add(g_done + mchunk, 1u);

    } else {
        // =================== GEMM3 ===================
        const int n0 = (role - 4) * 128;
        // wait for this m-chunk's states
        if (t == 0) {
            while (ld_acquire_u32(g_done + mchunk) != 4u) { }
        }
        __syncthreads();

        const __half* Ag = g_S16 + (size_t)(m0 + r0) * K3 + c0 * 8;
        const __half* Bg = g_Wc16 + (size_t)(n0 + r0) * K3 + c0 * 8;

        auto issue = [&](int slot, int kof) {
            uint32_t base = sb + slot * 16384;
            cp_async16(base + sAoff,        Ag + kof);
            cp_async16(base + sAoff + 4096, Ag + kof + (size_t)64 * K3);
            cp_async16(base + sAoff + 8192, Bg + kof);
            cp_async16(base + sAoff + 12288,Bg + kof + (size_t)64 * K3);
        };

        issue(0, 0);  CP_COMMIT();
        issue(1, 32); CP_COMMIT();
        issue(2, 64); CP_COMMIT();

        const int NIT = K3 / 32;   // 16
        for (int it = 0; it < NIT; ++it) {
            CP_WAIT(2);
            __syncthreads();
            uint32_t stg = sb + (it & 3) * 16384;
            MMA_STAGE(stg);
            if (it + 3 < NIT) issue((it + 3) & 3, (it + 3) * 32);
            CP_COMMIT();
        }

        // Epilogue with D*u feedthrough
#pragma unroll
        for (int mi = 0; mi < 2; ++mi) {
            int row0 = m0 + mBase + mi * 16 + g;
#pragma unroll
            for (int ni = 0; ni < 8; ++ni) {
                int col = n0 + nBase + ni * 8 + 2 * tig;
                float d0 = Dvec[col], d1 = Dvec[col + 1];
                float2 u0 = *(const float2*)(U + (size_t)row0 * HDIM + col);
                float2 u1 = *(const float2*)(U + (size_t)(row0 + 8) * HDIM + col);
                float2 v0 = make_float2(fmaf(d0, u0.x, acc[mi][ni][0]),
                                        fmaf(d1, u0.y, acc[mi][ni][1]));
                float2 v1 = make_float2(fmaf(d0, u1.x, acc[mi][ni][2]),
                                        fmaf(d1, u1.y, acc[mi][ni][3]));
                *(float2*)(C + (size_t)row0 * N3 + col) = v0;
                *(float2*)(C + (size_t)(row0 + 8) * N3 + col) = v1;
            }
        }
    }
}

// ---------------------------------------------------------------------------
extern "C" void kernel_launch(void* const* d_in, const int* in_sizes, int n_in,
                              void* d_out, int out_size)
{
    const float* u   = (const float*)d_in[0];
    const float* Lre = (const float*)d_in[1];
    const float* Lim = (const float*)d_in[2];
    const float* Bp  = (const float*)d_in[3];
    const float* Cp  = (const float*)d_in[4];
    const float* Dv  = (const float*)d_in[5];
    const float* lst = (const float*)d_in[6];
    float* out = (float*)d_out;

    cudaFuncSetAttribute(s5_fused,
                         cudaFuncAttributeMaxDynamicSharedMemorySize, FU_SMEM);

    // 1. constants (3 transcendentals/thread + fp64 mult chains);
    //    fp32 weight packing; u->fp16 + flag clear
    s5_const_kernel<<<8, 32>>>(Lre, Lim, lst);
    s5_pack_kernel<<<PDIM, HDIM>>>(Bp, Cp);
    s5_u2h_kernel<<<(MROWS * HDIM) / 2048, 256>>>(u);

    // 2. fused: Bu GEMM + full scan + output GEMM (dataflow-synchronized)
    s5_fused<<<NMCH * 6, 256, FU_SMEM>>>(out, Dv, u);
}

// round 15
// speedup vs baseline: 1.6833x; 1.0556x over previous
#include <cuda_runtime.h>
#include <cuda_fp16.h>
#include <math.h>
#include <stdint.h>

// Problem dims
#define BSZ   16
#define LSEQ  1024
#define HDIM  256
#define PDIM  256
#define MROWS (BSZ*LSEQ)     // 16384
#define N1    (2*PDIM)       // 512  (interleaved re/im: col 2p, 2p+1)
#define K1    HDIM           // 256
#define N3    HDIM           // 256
#define K3    (2*PDIM)       // 512
#define CHUNK 128            // == GEMM tile M
#define NCH   (LSEQ/CHUNK)   // 8
#define NMCH  (MROWS/CHUNK)  // 128 m-chunks

// Scratch (static device memory; no allocations allowed)
__device__ __align__(128) __half g_S16[(size_t)MROWS * N1];  // 16 MB: final states fp16
__device__ __align__(128) __half g_u16[(size_t)MROWS * HDIM];// 8 MB: u in fp16
__device__ __align__(128) __half g_Wb16[N1 * K1];            // (512,256) N-major, K-contig
__device__ __align__(128) __half g_Wc16[N3 * K3];            // (256,512) N-major, K-contig
__device__ float2 g_coef[PDIM];                              // scaled (Lambda_bar-1)/Lambda
__device__ float g_lam_re[PDIM], g_lam_im[PDIM];
__device__ float g_lam32_re[PDIM], g_lam32_im[PDIM];         // lam^32
__device__ float g_pow32_re[4][PDIM], g_pow32_im[4][PDIM];   // lam^(32q)
__device__ float g_powT_re[NCH][PDIM], g_powT_im[NCH][PDIM]; // lam^(128j)
__device__ float g_inv_scl[PDIM];
__device__ __align__(128) float    g_car[BSZ * NCH * PDIM * 2]; // chunk aggregates
__device__ __align__(128) unsigned g_flag[BSZ * NCH * PDIM];    // per-p publish flags
__device__ __align__(128) unsigned g_done[NMCH];                // per-m-chunk S16-ready count

// ---------------------------------------------------------------------------
// helpers
// ---------------------------------------------------------------------------
__device__ __forceinline__ uint32_t smem_u32(const void* p) {
    uint32_t a;
    asm("{ .reg .u64 t; cvta.to.shared.u64 t, %1; cvt.u32.u64 %0, t; }" : "=r"(a) : "l"(p));
    return a;
}
__device__ __forceinline__ uint32_t f2h2(float a, float b) {   // lo=a, hi=b
    uint32_t r;
    asm("cvt.rn.f16x2.f32 %0, %1, %2;" : "=r"(r) : "f"(b), "f"(a));
    return r;
}
__device__ __forceinline__ void cp_async16(uint32_t saddr, const void* gaddr) {
    asm volatile("cp.async.cg.shared.global [%0], [%1], 16;" :: "r"(saddr), "l"(gaddr));
}
#define CP_COMMIT() asm volatile("cp.async.commit_group;" ::: "memory")
#define CP_WAIT(n)  asm volatile("cp.async.wait_group %0;" :: "n"(n) : "memory")

__device__ __forceinline__ void st_release_u32(unsigned* p, unsigned v) {
    asm volatile("st.release.gpu.global.u32 [%0], %1;" :: "l"(p), "r"(v) : "memory");
}
__device__ __forceinline__ unsigned ld_acquire_u32(const unsigned* p) {
    unsigned v;
    asm volatile("ld.acquire.gpu.global.u32 %0, [%1];" : "=r"(v) : "l"(p) : "memory");
    return v;
}
__device__ __forceinline__ void red_release_add(unsigned* p, unsigned v) {
    asm volatile("red.release.gpu.global.add.u32 [%0], %1;" :: "l"(p), "r"(v) : "memory");
}
__device__ __forceinline__ float2 ld_relaxed_f2(const float* p) {
    float2 v;
    asm volatile("ld.relaxed.gpu.global.v2.f32 {%0,%1}, [%2];"
                 : "=f"(v.x), "=f"(v.y) : "l"(p) : "memory");
    return v;
}

__device__ __forceinline__ void ldsm4(uint32_t& r0, uint32_t& r1, uint32_t& r2,
                                      uint32_t& r3, uint32_t addr) {
    asm volatile("ldmatrix.sync.aligned.m8n8.x4.shared.b16 {%0,%1,%2,%3}, [%4];"
                 : "=r"(r0), "=r"(r1), "=r"(r2), "=r"(r3) : "r"(addr));
}
__device__ __forceinline__ void mma16816(float c[4], const uint32_t a[4],
                                         uint32_t b0, uint32_t b1) {
    asm volatile(
        "mma.sync.aligned.m16n8k16.row.col.f32.f16.f16.f32 "
        "{%0,%1,%2,%3}, {%4,%5,%6,%7}, {%8,%9}, {%0,%1,%2,%3};"
        : "+f"(c[0]), "+f"(c[1]), "+f"(c[2]), "+f"(c[3])
        : "r"(a[0]), "r"(a[1]), "r"(a[2]), "r"(a[3]), "r"(b0), "r"(b1));
}

// MMA block on one 32-k stage.  ALL 12 ldsm issued up front (independent ->
// one latency exposure), then 32 back-to-back mma.  64B rows, chunk^((r>>1)&3).
#define MMA_STAGE(stgAddr)                                                    \
    do {                                                                      \
        uint32_t af[2][2][4], bf[2][4][4];                                    \
        _Pragma("unroll")                                                     \
        for (int ks = 0; ks < 2; ++ks) {                                      \
            const int cbase = ks * 2;                                         \
            _Pragma("unroll")                                                 \
            for (int mi = 0; mi < 2; ++mi) {                                  \
                int ml = mBase + mi * 16 + (lane & 15);                       \
                int ci = (cbase + (lane >> 4)) ^ ((ml >> 1) & 3);             \
                ldsm4(af[ks][mi][0], af[ks][mi][1], af[ks][mi][2],            \
                      af[ks][mi][3], (stgAddr) + ml * 64 + ci * 16);          \
            }                                                                 \
            _Pragma("unroll")                                                 \
            for (int nj = 0; nj < 4; ++nj) {                                  \
                int nl = nBase + nj * 16 + ((lane >> 4) & 1) * 8 + (lane & 7);\
                int ci = (cbase + ((lane >> 3) & 1)) ^ ((nl >> 1) & 3);       \
                ldsm4(bf[ks][nj][0], bf[ks][nj][1], bf[ks][nj][2],            \
                      bf[ks][nj][3], (stgAddr) + 8192 + nl * 64 + ci * 16);   \
            }                                                                 \
        }                                                                     \
        _Pragma("unroll")                                                     \
        for (int ks = 0; ks < 2; ++ks)                                        \
            _Pragma("unroll")                                                 \
            for (int mi = 0; mi < 2; ++mi)                                    \
                _Pragma("unroll")                                             \
                for (int nj = 0; nj < 4; ++nj) {                              \
                    mma16816(acc[mi][nj * 2 + 0], af[ks][mi],                 \
                             bf[ks][nj][0], bf[ks][nj][1]);                   \
                    mma16816(acc[mi][nj * 2 + 1], af[ks][mi],                 \
                             bf[ks][nj][2], bf[ks][nj][3]);                   \
                }                                                             \
    } while (0)

// ---------------------------------------------------------------------------
// Per-p constants.  Only 3 fp64 transcendentals/thread; powers via fp64
// complex mult chains (err ~1e-15).  grid = 8, block = 32.
// ---------------------------------------------------------------------------
__global__ void s5_const_kernel(const float* __restrict__ Lre,
                                const float* __restrict__ Lim,
                                const float* __restrict__ lstep)
{
    int p = blockIdx.x * 32 + threadIdx.x;

    double lre = (double)Lre[p], lim = (double)Lim[p];
    double delta = exp((double)lstep[p]);            // transcendental 1
    double a = lre * delta, b = lim * delta;
    double ea = exp(a);                              // transcendental 2
    double sb_, cb_;
    sincos(b, &sb_, &cb_);                           // transcendental 3
    double lam_r = ea * cb_;
    double lam_i = ea * sb_;

    double d2 = lre * lre + lim * lim;
    double nr = lam_r - 1.0, ni = lam_i;
    double cr = (nr * lre + ni * lim) / d2;
    double ci = (ni * lre - nr * lim) / d2;
    int e;
    frexp(sqrt(cr * cr + ci * ci), &e);
    double scl = ldexp(1.0, -e);
    g_coef[p] = make_float2((float)(cr * scl), (float)(ci * scl));
    g_inv_scl[p] = (float)ldexp(1.0, e);

    g_lam_re[p] = (float)lam_r;
    g_lam_im[p] = (float)lam_i;

    // lam^32 via 5 complex squarings
    double xr = lam_r, xi = lam_i;
#pragma unroll
    for (int i = 0; i < 5; ++i) {
        double tr = xr * xr - xi * xi;
        double ti = 2.0 * xr * xi;
        xr = tr; xi = ti;
    }
    g_lam32_re[p] = (float)xr;
    g_lam32_im[p] = (float)xi;

    double p2r = xr * xr - xi * xi, p2i = 2.0 * xr * xi;          // lam^64
    double p3r = p2r * xr - p2i * xi, p3i = p2r * xi + p2i * xr;  // lam^96
    g_pow32_re[0][p] = 1.0f;        g_pow32_im[0][p] = 0.0f;
    g_pow32_re[1][p] = (float)xr;   g_pow32_im[1][p] = (float)xi;
    g_pow32_re[2][p] = (float)p2r;  g_pow32_im[2][p] = (float)p2i;
    g_pow32_re[3][p] = (float)p3r;  g_pow32_im[3][p] = (float)p3i;

    double l128r = p2r * p2r - p2i * p2i;
    double l128i = 2.0 * p2r * p2i;
    double tr = 1.0, ti = 0.0;
#pragma unroll
    for (int j = 0; j < NCH; ++j) {
        g_powT_re[j][p] = (float)tr;
        g_powT_im[j][p] = (float)ti;
        double ntr = tr * l128r - ti * l128i;
        double nti = tr * l128i + ti * l128r;
        tr = ntr; ti = nti;
    }
}

// ---------------------------------------------------------------------------
// Fused prep: u->fp16 + flag/done clear (blocks 0..2047) + fp16 weight
// packing (blocks 2048..2303).  grid = 2304, block = 256.
// ---------------------------------------------------------------------------
__global__ void s5_prep_kernel(const float* __restrict__ u,
                               const float* __restrict__ Bp,
                               const float* __restrict__ Cp)
{
    if (blockIdx.x < 2048) {
        size_t i = ((size_t)blockIdx.x * 256 + threadIdx.x) * 8;
        float4 a = *(const float4*)(u + i);
        float4 b = *(const float4*)(u + i + 4);
        *(uint4*)(g_u16 + i) = make_uint4(f2h2(a.x, a.y), f2h2(a.z, a.w),
                                          f2h2(b.x, b.y), f2h2(b.z, b.w));
        if (blockIdx.x < 32) {   // clear 32768 flags (8192 uint4)
            ((uint4*)g_flag)[blockIdx.x * 256 + threadIdx.x] =
                make_uint4(0u, 0u, 0u, 0u);
        }
        if (blockIdx.x == 32 && threadIdx.x < NMCH) g_done[threadIdx.x] = 0u;
    } else {
        int p = blockIdx.x - 2048;
        int h = threadIdx.x;
        float2 cf = g_coef[p];

        float br = Bp[((size_t)p * HDIM + h) * 2 + 0];
        float bi = Bp[((size_t)p * HDIM + h) * 2 + 1];
        g_Wb16[(size_t)(2 * p) * K1 + h]     = __float2half(cf.x * br - cf.y * bi);
        g_Wb16[(size_t)(2 * p + 1) * K1 + h] = __float2half(cf.x * bi + cf.y * br);

        float ccr = Cp[((size_t)h * PDIM + p) * 2 + 0];
        float cci = Cp[((size_t)h * PDIM + p) * 2 + 1];
        g_Wc16[(size_t)h * K3 + 2 * p]     = __float2half( 2.0f * ccr);
        g_Wc16[(size_t)h * K3 + 2 * p + 1] = __float2half(-2.0f * cci);
    }
}

// ---------------------------------------------------------------------------
// FUSED kernel: 768 blocks, 6 roles per m-chunk: r<4 GEMM1+scan, r>=4 GEMM3.
// Dataflow-synchronized via per-m-chunk release counters (deadlock-free:
// waits target strictly lower bids).
// ---------------------------------------------------------------------------
#define FU_SMEM 70656

__global__ void __launch_bounds__(256, 2)
s5_fused(float* __restrict__ C,
         const float* __restrict__ Dvec,
         const float* __restrict__ U)
{
    extern __shared__ char sm[];
    uint32_t sb = smem_u32(sm);

    const int bid = blockIdx.x;
    const int mchunk = bid / 6;
    const int role = bid % 6;

    const int t = threadIdx.x;
    const int lane = t & 31, w = t >> 5;
    const int g = lane >> 2, tig = lane & 3;
    const int mBase = (w & 3) * 32;
    const int nBase = (w >> 2) * 64;
    const int m0 = mchunk * 128;

    const int r0 = t >> 2, c0 = t & 3;
    const uint32_t sAoff = r0 * 64 + (((uint32_t)(c0 ^ ((r0 >> 1) & 3))) << 4);

    float acc[2][8][4];
#pragma unroll
    for (int mi = 0; mi < 2; ++mi)
#pragma unroll
        for (int ni = 0; ni < 8; ++ni)
#pragma unroll
            for (int q = 0; q < 4; ++q) acc[mi][ni][q] = 0.0f;

    if (role < 4) {
        // =================== GEMM1 + fused scan ===================
        const int n0 = role * 128;
        const int bIdx = m0 >> 10, cIdx = (m0 >> 7) & (NCH - 1);
        const __half* Ag = g_u16 + (size_t)(m0 + r0) * K1 + c0 * 8;
        const __half* Bg = g_Wb16 + (size_t)(n0 + r0) * K1 + c0 * 8;

        auto issue = [&](int slot, int kof) {
            uint32_t base = sb + slot * 16384;
            cp_async16(base + sAoff,        Ag + kof);
            cp_async16(base + sAoff + 4096, Ag + kof + (size_t)64 * K1);
            cp_async16(base + sAoff + 8192, Bg + kof);
            cp_async16(base + sAoff + 12288,Bg + kof + (size_t)64 * K1);
        };

        issue(0, 0);  CP_COMMIT();
        issue(1, 32); CP_COMMIT();
        issue(2, 64); CP_COMMIT();

        const int NIT = K1 / 32;   // 8
        for (int it = 0; it < NIT; ++it) {
            CP_WAIT(2);
            __syncthreads();
            uint32_t stg = sb + (it & 3) * 16384;
            MMA_STAGE(stg);
            if (it + 3 < NIT) issue((it + 3) & 3, (it + 3) * 32);
            CP_COMMIT();
        }
        CP_WAIT(0);
        __syncthreads();   // pipeline smem dead; reuse as Stile

        float* Stile = (float*)sm;              // 128 x 130
        float* carrR = (float*)(sm + 66560);    // [4][64]  (later: E_chunk)
        float* carrI = carrR + 256;
        float* prefR = carrI + 256;             // [4][64]
        float* prefI = prefR + 256;

        // 1. accs -> Stile
#pragma unroll
        for (int mi = 0; mi < 2; ++mi) {
            int row = mBase + mi * 16 + g;
#pragma unroll
            for (int ni = 0; ni < 8; ++ni) {
                int col = nBase + ni * 8 + 2 * tig;
                *(float2*)(Stile + row * 130 + col) =
                    make_float2(acc[mi][ni][0], acc[mi][ni][1]);
                *(float2*)(Stile + (row + 8) * 130 + col) =
                    make_float2(acc[mi][ni][2], acc[mi][ni][3]);
            }
        }
        __syncthreads();

        // 2. segment-local scan (zero init), 4 segs x 64 complex cols
        const int pl = t & 63, seg = t >> 6;
        const int pg = (n0 >> 1) + pl;
        const float lr = g_lam_re[pg], li = g_lam_im[pg];
        {
            float yr = 0.f, yi = 0.f;
            float* colp = Stile + 2 * pl;
#pragma unroll 4
            for (int tt = 0; tt < 32; ++tt) {
                int row = seg * 32 + tt;
                float2 s = *(float2*)(colp + row * 130);
                float nyr = fmaf(lr, yr, fmaf(-li, yi, s.x));
                float nyi = fmaf(lr, yi, fmaf( li, yr, s.y));
                yr = nyr; yi = nyi;
                *(float2*)(colp + row * 130) = make_float2(yr, yi);
            }
            carrR[seg * 64 + pl] = yr;
            carrI[seg * 64 + pl] = yi;
        }
        __syncthreads();

        // 3. seg-carry combine -> chunk aggregate; publish; lookback.
        if (t < 64) {
            int pg2 = (n0 >> 1) + t;
            float l32r = g_lam32_re[pg2], l32i = g_lam32_im[pg2];
            float Pr = 0.f, Pi = 0.f;
            float sp[4][2];
#pragma unroll
            for (int q = 0; q < 4; ++q) {
                sp[q][0] = Pr; sp[q][1] = Pi;
                float cr = carrR[q * 64 + t], ci = carrI[q * 64 + t];
                float nPr = fmaf(l32r, Pr, fmaf(-l32i, Pi, cr));
                float nPi = fmaf(l32r, Pi, fmaf( l32i, Pr, ci));
                Pr = nPr; Pi = nPi;
            }
            size_t ci0 = (size_t)(bIdx * NCH + cIdx) * PDIM + pg2;
            *(float2*)(g_car + 2 * ci0) = make_float2(Pr, Pi);
            st_release_u32(g_flag + ci0, 1u);

            float Ecr = 0.f, Eci = 0.f;
            for (int j = 0; j < cIdx; ++j) {
                int d = cIdx - 1 - j;
                size_t fj = (size_t)(bIdx * NCH + j) * PDIM + pg2;
                while (ld_acquire_u32(g_flag + fj) == 0) { }
                float2 cv = ld_relaxed_f2(g_car + 2 * fj);
                float pr = g_powT_re[d][pg2], pi = g_powT_im[d][pg2];
                Ecr = fmaf(pr, cv.x, fmaf(-pi, cv.y, Ecr));
                Eci = fmaf(pr, cv.y, fmaf( pi, cv.x, Eci));
            }
#pragma unroll
            for (int q = 0; q < 4; ++q) {
                prefR[q * 64 + t] = sp[q][0];
                prefI[q * 64 + t] = sp[q][1];
            }
            carrR[t] = Ecr;
            carrI[t] = Eci;
        }
        __syncthreads();

        // 4. total prefix apply + fp16 convert, write final states to g_S16
        {
            float Ecr = carrR[pl], Eci = carrI[pl];
            float p32r = g_pow32_re[seg][pg], p32i = g_pow32_im[seg][pg];
            float Er = prefR[seg * 64 + pl] + p32r * Ecr - p32i * Eci;
            float Ei = prefI[seg * 64 + pl] + p32r * Eci + p32i * Ecr;
            float inv = g_inv_scl[pg];
            float wr = lr, wi = li;
            float* colp = Stile + 2 * pl;
            __half2* op = (__half2*)g_S16 + (size_t)m0 * PDIM + pg;
#pragma unroll 4
            for (int tt = 0; tt < 32; ++tt) {
                int row = seg * 32 + tt;
                float2 s = *(float2*)(colp + row * 130);
                float xr = fmaf(wr, Er, fmaf(-wi, Ei, s.x));
                float xi = fmaf(wr, Ei, fmaf( wi, Er, s.y));
                op[(size_t)row * PDIM] = __floats2half2_rn(xr * inv, xi * inv);
                float nwr = fmaf(wr, lr, -wi * li);
                float nwi = fmaf(wr, li,  wi * lr);
                wr = nwr; wi = nwi;
            }
        }
        // publish S16-chunk readiness
        __threadfence();
        __syncthreads();
        if (t == 0) red_release_add(g_done + mchunk, 1u);

    } else {
        // =================== GEMM3 ===================
        const int n0 = (role - 4) * 128;
        if (t == 0) {
            while (ld_acquire_u32(g_done + mchunk) != 4u) { }
        }
        __syncthreads();

        const __half* Ag = g_S16 + (size_t)(m0 + r0) * K3 + c0 * 8;
        const __half* Bg = g_Wc16 + (size_t)(n0 + r0) * K3 + c0 * 8;

        auto issue = [&](int slot, int kof) {
            uint32_t base = sb + slot * 16384;
            cp_async16(base + sAoff,        Ag + kof);
            cp_async16(base + sAoff + 4096, Ag + kof + (size_t)64 * K3);
            cp_async16(base + sAoff + 8192, Bg + kof);
            cp_async16(base + sAoff + 12288,Bg + kof + (size_t)64 * K3);
        };

        issue(0, 0);  CP_COMMIT();
        issue(1, 32); CP_COMMIT();
        issue(2, 64); CP_COMMIT();

        const int NIT = K3 / 32;   // 16
        for (int it = 0; it < NIT; ++it) {
            CP_WAIT(2);
            __syncthreads();
            uint32_t stg = sb + (it & 3) * 16384;
            MMA_STAGE(stg);
            if (it + 3 < NIT) issue((it + 3) & 3, (it + 3) * 32);
            CP_COMMIT();
        }

        // Epilogue with D*u feedthrough
#pragma unroll
        for (int mi = 0; mi < 2; ++mi) {
            int row0 = m0 + mBase + mi * 16 + g;
#pragma unroll
            for (int ni = 0; ni < 8; ++ni) {
                int col = n0 + nBase + ni * 8 + 2 * tig;
                float d0 = Dvec[col], d1 = Dvec[col + 1];
                float2 u0 = *(const float2*)(U + (size_t)row0 * HDIM + col);
                float2 u1 = *(const float2*)(U + (size_t)(row0 + 8) * HDIM + col);
                float2 v0 = make_float2(fmaf(d0, u0.x, acc[mi][ni][0]),
                                        fmaf(d1, u0.y, acc[mi][ni][1]));
                float2 v1 = make_float2(fmaf(d0, u1.x, acc[mi][ni][2]),
                                        fmaf(d1, u1.y, acc[mi][ni][3]));
                *(float2*)(C + (size_t)row0 * N3 + col) = v0;
                *(float2*)(C + (size_t)(row0 + 8) * N3 + col) = v1;
            }
        }
    }
}

// ---------------------------------------------------------------------------
extern "C" void kernel_launch(void* const* d_in, const int* in_sizes, int n_in,
                              void* d_out, int out_size)
{
    const float* u   = (const float*)d_in[0];
    const float* Lre = (const float*)d_in[1];
    const float* Lim = (const float*)d_in[2];
    const float* Bp  = (const float*)d_in[3];
    const float* Cp  = (const float*)d_in[4];
    const float* Dv  = (const float*)d_in[5];
    const float* lst = (const float*)d_in[6];
    float* out = (float*)d_out;

    cudaFuncSetAttribute(s5_fused,
                         cudaFuncAttributeMaxDynamicSharedMemorySize, FU_SMEM);

    // 1. constants (3 transcendentals/thread);  fused u->fp16 + flags + pack
    s5_const_kernel<<<8, 32>>>(Lre, Lim, lst);
    s5_prep_kernel<<<2304, 256>>>(u, Bp, Cp);

    // 2. fused: Bu GEMM + full scan + output GEMM (dataflow-synchronized)
    s5_fused<<<NMCH * 6, 256, FU_SMEM>>>(out, Dv, u);
}

// round 16
// speedup vs baseline: 1.6923x; 1.0053x over previous
#include <cuda_runtime.h>
#include <cuda_fp16.h>
#include <math.h>
#include <stdint.h>

// Problem dims
#define BSZ   16
#define LSEQ  1024
#define HDIM  256
#define PDIM  256
#define MROWS (BSZ*LSEQ)     // 16384
#define N1    (2*PDIM)       // 512  (interleaved re/im: col 2p, 2p+1)
#define K1    HDIM           // 256
#define N3    HDIM           // 256
#define K3    (2*PDIM)       // 512
#define CHUNK 128            // == GEMM tile M
#define NCH   (LSEQ/CHUNK)   // 8
#define NMCH  (MROWS/CHUNK)  // 128 m-chunks

// Scratch (static device memory; no allocations allowed)
__device__ __align__(128) __half g_S16[(size_t)MROWS * N1];  // 16 MB: final states fp16
__device__ __align__(128) __half g_u16[(size_t)MROWS * HDIM];// 8 MB: u in fp16
__device__ __align__(128) __half g_Wb16[N1 * K1];            // (512,256) N-major, K-contig
__device__ __align__(128) __half g_Wc16[N3 * K3];            // (256,512) N-major, K-contig
__device__ float g_lam_re[PDIM], g_lam_im[PDIM];
__device__ float g_lam32_re[PDIM], g_lam32_im[PDIM];         // lam^32
__device__ float g_pow32_re[4][PDIM], g_pow32_im[4][PDIM];   // lam^(32q)
__device__ float g_powT_re[NCH][PDIM], g_powT_im[NCH][PDIM]; // lam^(128j)
__device__ float g_inv_scl[PDIM];
__device__ __align__(128) float    g_car[BSZ * NCH * PDIM * 2]; // chunk aggregates
__device__ __align__(128) unsigned g_flag[BSZ * NCH * PDIM];    // per-p publish flags
__device__ __align__(128) unsigned g_done[NMCH];                // per-m-chunk S16-ready count

// ---------------------------------------------------------------------------
// helpers
// ---------------------------------------------------------------------------
__device__ __forceinline__ uint32_t smem_u32(const void* p) {
    uint32_t a;
    asm("{ .reg .u64 t; cvta.to.shared.u64 t, %1; cvt.u32.u64 %0, t; }" : "=r"(a) : "l"(p));
    return a;
}
__device__ __forceinline__ uint32_t f2h2(float a, float b) {   // lo=a, hi=b
    uint32_t r;
    asm("cvt.rn.f16x2.f32 %0, %1, %2;" : "=r"(r) : "f"(b), "f"(a));
    return r;
}
__device__ __forceinline__ void cp_async16(uint32_t saddr, const void* gaddr) {
    asm volatile("cp.async.cg.shared.global [%0], [%1], 16;" :: "r"(saddr), "l"(gaddr));
}
#define CP_COMMIT() asm volatile("cp.async.commit_group;" ::: "memory")
#define CP_WAIT(n)  asm volatile("cp.async.wait_group %0;" :: "n"(n) : "memory")

__device__ __forceinline__ void st_release_u32(unsigned* p, unsigned v) {
    asm volatile("st.release.gpu.global.u32 [%0], %1;" :: "l"(p), "r"(v) : "memory");
}
__device__ __forceinline__ unsigned ld_acquire_u32(const unsigned* p) {
    unsigned v;
    asm volatile("ld.acquire.gpu.global.u32 %0, [%1];" : "=r"(v) : "l"(p) : "memory");
    return v;
}
__device__ __forceinline__ void red_release_add(unsigned* p, unsigned v) {
    asm volatile("red.release.gpu.global.add.u32 [%0], %1;" :: "l"(p), "r"(v) : "memory");
}
__device__ __forceinline__ float2 ld_relaxed_f2(const float* p) {
    float2 v;
    asm volatile("ld.relaxed.gpu.global.v2.f32 {%0,%1}, [%2];"
                 : "=f"(v.x), "=f"(v.y) : "l"(p) : "memory");
    return v;
}

__device__ __forceinline__ void ldsm4(uint32_t& r0, uint32_t& r1, uint32_t& r2,
                                      uint32_t& r3, uint32_t addr) {
    asm volatile("ldmatrix.sync.aligned.m8n8.x4.shared.b16 {%0,%1,%2,%3}, [%4];"
                 : "=r"(r0), "=r"(r1), "=r"(r2), "=r"(r3) : "r"(addr));
}
__device__ __forceinline__ void mma16816(float c[4], const uint32_t a[4],
                                         uint32_t b0, uint32_t b1) {
    asm volatile(
        "mma.sync.aligned.m16n8k16.row.col.f32.f16.f16.f32 "
        "{%0,%1,%2,%3}, {%4,%5,%6,%7}, {%8,%9}, {%0,%1,%2,%3};"
        : "+f"(c[0]), "+f"(c[1]), "+f"(c[2]), "+f"(c[3])
        : "r"(a[0]), "r"(a[1]), "r"(a[2]), "r"(a[3]), "r"(b0), "r"(b1));
}

// MMA block on one 32-k stage.  ALL 12 ldsm issued up front (independent ->
// one latency exposure), then 32 back-to-back mma.  64B rows, chunk^((r>>1)&3).
#define MMA_STAGE(stgAddr)                                                    \
    do {                                                                      \
        uint32_t af[2][2][4], bf[2][4][4];                                    \
        _Pragma("unroll")                                                     \
        for (int ks = 0; ks < 2; ++ks) {                                      \
            const int cbase = ks * 2;                                         \
            _Pragma("unroll")                                                 \
            for (int mi = 0; mi < 2; ++mi) {                                  \
                int ml = mBase + mi * 16 + (lane & 15);                       \
                int ci = (cbase + (lane >> 4)) ^ ((ml >> 1) & 3);             \
                ldsm4(af[ks][mi][0], af[ks][mi][1], af[ks][mi][2],            \
                      af[ks][mi][3], (stgAddr) + ml * 64 + ci * 16);          \
            }                                                                 \
            _Pragma("unroll")                                                 \
            for (int nj = 0; nj < 4; ++nj) {                                  \
                int nl = nBase + nj * 16 + ((lane >> 4) & 1) * 8 + (lane & 7);\
                int ci = (cbase + ((lane >> 3) & 1)) ^ ((nl >> 1) & 3);       \
                ldsm4(bf[ks][nj][0], bf[ks][nj][1], bf[ks][nj][2],            \
                      bf[ks][nj][3], (stgAddr) + 8192 + nl * 64 + ci * 16);   \
            }                                                                 \
        }                                                                     \
        _Pragma("unroll")                                                     \
        for (int ks = 0; ks < 2; ++ks)                                        \
            _Pragma("unroll")                                                 \
            for (int mi = 0; mi < 2; ++mi)                                    \
                _Pragma("unroll")                                             \
                for (int nj = 0; nj < 4; ++nj) {                              \
                    mma16816(acc[mi][nj * 2 + 0], af[ks][mi],                 \
                             bf[ks][nj][0], bf[ks][nj][1]);                   \
                    mma16816(acc[mi][nj * 2 + 1], af[ks][mi],                 \
                             bf[ks][nj][2], bf[ks][nj][3]);                   \
                }                                                             \
    } while (0)

// ---------------------------------------------------------------------------
// ONE prep kernel, fully parallel (no serialized fp64 chains):
//   blocks [0,2048):     u -> fp16 (8 floats/thread) + flag/done clear
//   blocks [2048,2304):  weight packing; block computes its own coef[p]
//                        (3 fp64 transcendentals on thread 0, smem bcast)
//   blocks [2304,2316):  power tables; thread = p, block = entry:
//                        e=0: lam, inv_scl, pow32[0], powT[0]
//                        e=1..3: pow32[e] (x=32e; e==1 also lam32)
//                        e=4..10: powT[e-3] (x=128(e-3))
//                        e=11: powT[... wait mapping below] -- j=1..7 needs 7
//   mapping: e in 1..3 -> pow32[e]; e in 4..10 -> powT[e-3] (j=1..7).
//   (12 blocks: e=0..10 used, e=11 idle-exit.)
// grid = 2316, block = 256.
// ---------------------------------------------------------------------------
__global__ void s5_prep_kernel(const float* __restrict__ u,
                               const float* __restrict__ Bp,
                               const float* __restrict__ Cp,
                               const float* __restrict__ Lre,
                               const float* __restrict__ Lim,
                               const float* __restrict__ lstep)
{
    if (blockIdx.x < 2048) {
        size_t i = ((size_t)blockIdx.x * 256 + threadIdx.x) * 8;
        float4 a = *(const float4*)(u + i);
        float4 b = *(const float4*)(u + i + 4);
        *(uint4*)(g_u16 + i) = make_uint4(f2h2(a.x, a.y), f2h2(a.z, a.w),
                                          f2h2(b.x, b.y), f2h2(b.z, b.w));
        if (blockIdx.x < 32) {   // clear 32768 flags (8192 uint4)
            ((uint4*)g_flag)[blockIdx.x * 256 + threadIdx.x] =
                make_uint4(0u, 0u, 0u, 0u);
        }
        if (blockIdx.x == 32 && threadIdx.x < NMCH) g_done[threadIdx.x] = 0u;
    } else if (blockIdx.x < 2304) {
        // ---- weight packing; compute own coef[p] ----
        int p = blockIdx.x - 2048;
        int h = threadIdx.x;
        __shared__ float2 cfs;
        __shared__ float invs;
        if (h == 0) {
            double lre = (double)Lre[p], lim = (double)Lim[p];
            double delta = exp((double)lstep[p]);
            double a = lre * delta, b = lim * delta;
            double ea = exp(a);
            double sb_, cb_;
            sincos(b, &sb_, &cb_);
            double lam_r = ea * cb_, lam_i = ea * sb_;
            double d2 = lre * lre + lim * lim;
            double nr = lam_r - 1.0, ni = lam_i;
            double cr = (nr * lre + ni * lim) / d2;
            double ci = (ni * lre - nr * lim) / d2;
            int e;
            frexp(sqrt(cr * cr + ci * ci), &e);
            double scl = ldexp(1.0, -e);
            cfs = make_float2((float)(cr * scl), (float)(ci * scl));
            invs = (float)ldexp(1.0, e);
            g_inv_scl[p] = invs;
        }
        __syncthreads();
        float2 cf = cfs;

        float br = Bp[((size_t)p * HDIM + h) * 2 + 0];
        float bi = Bp[((size_t)p * HDIM + h) * 2 + 1];
        g_Wb16[(size_t)(2 * p) * K1 + h]     = __float2half(cf.x * br - cf.y * bi);
        g_Wb16[(size_t)(2 * p + 1) * K1 + h] = __float2half(cf.x * bi + cf.y * br);

        float ccr = Cp[((size_t)h * PDIM + p) * 2 + 0];
        float cci = Cp[((size_t)h * PDIM + p) * 2 + 1];
        g_Wc16[(size_t)h * K3 + 2 * p]     = __float2half( 2.0f * ccr);
        g_Wc16[(size_t)h * K3 + 2 * p + 1] = __float2half(-2.0f * cci);
    } else {
        // ---- power tables: lam^x = exp(x a) cis(x b), one thread per (p,e) ----
        int e = blockIdx.x - 2304;          // 0..11
        if (e > 10) return;
        int p = threadIdx.x;

        double lre = (double)Lre[p], lim = (double)Lim[p];
        double delta = exp((double)lstep[p]);
        double a = lre * delta, b = lim * delta;

        double x;
        if (e == 0) x = 1.0;
        else if (e <= 3) x = 32.0 * e;
        else x = 128.0 * (e - 3);

        double ex = exp(x * a);
        double sb_, cb_;
        sincos(x * b, &sb_, &cb_);
        float vr = (float)(ex * cb_), vi = (float)(ex * sb_);

        if (e == 0) {
            g_lam_re[p] = vr;       g_lam_im[p] = vi;
            g_pow32_re[0][p] = 1.0f; g_pow32_im[0][p] = 0.0f;
            g_powT_re[0][p] = 1.0f;  g_powT_im[0][p] = 0.0f;
        } else if (e <= 3) {
            g_pow32_re[e][p] = vr;  g_pow32_im[e][p] = vi;
            if (e == 1) { g_lam32_re[p] = vr; g_lam32_im[p] = vi; }
        } else {
            g_powT_re[e - 3][p] = vr;
            g_powT_im[e - 3][p] = vi;
        }
    }
}

// ---------------------------------------------------------------------------
// FUSED kernel: 768 blocks, 6 roles per m-chunk: r<4 GEMM1+scan, r>=4 GEMM3.
// Dataflow-synchronized via per-m-chunk release counters (deadlock-free:
// waits target strictly lower bids).
// ---------------------------------------------------------------------------
#define FU_SMEM 70656

__global__ void __launch_bounds__(256, 2)
s5_fused(float* __restrict__ C,
         const float* __restrict__ Dvec,
         const float* __restrict__ U)
{
    extern __shared__ char sm[];
    uint32_t sb = smem_u32(sm);

    const int bid = blockIdx.x;
    const int mchunk = bid / 6;
    const int role = bid % 6;

    const int t = threadIdx.x;
    const int lane = t & 31, w = t >> 5;
    const int g = lane >> 2, tig = lane & 3;
    const int mBase = (w & 3) * 32;
    const int nBase = (w >> 2) * 64;
    const int m0 = mchunk * 128;

    const int r0 = t >> 2, c0 = t & 3;
    const uint32_t sAoff = r0 * 64 + (((uint32_t)(c0 ^ ((r0 >> 1) & 3))) << 4);

    float acc[2][8][4];
#pragma unroll
    for (int mi = 0; mi < 2; ++mi)
#pragma unroll
        for (int ni = 0; ni < 8; ++ni)
#pragma unroll
            for (int q = 0; q < 4; ++q) acc[mi][ni][q] = 0.0f;

    if (role < 4) {
        // =================== GEMM1 + fused scan ===================
        const int n0 = role * 128;
        const int bIdx = m0 >> 10, cIdx = (m0 >> 7) & (NCH - 1);
        const __half* Ag = g_u16 + (size_t)(m0 + r0) * K1 + c0 * 8;
        const __half* Bg = g_Wb16 + (size_t)(n0 + r0) * K1 + c0 * 8;

        auto issue = [&](int slot, int kof) {
            uint32_t base = sb + slot * 16384;
            cp_async16(base + sAoff,        Ag + kof);
            cp_async16(base + sAoff + 4096, Ag + kof + (size_t)64 * K1);
            cp_async16(base + sAoff + 8192, Bg + kof);
            cp_async16(base + sAoff + 12288,Bg + kof + (size_t)64 * K1);
        };

        issue(0, 0);  CP_COMMIT();
        issue(1, 32); CP_COMMIT();
        issue(2, 64); CP_COMMIT();

        const int NIT = K1 / 32;   // 8
        for (int it = 0; it < NIT; ++it) {
            CP_WAIT(2);
            __syncthreads();
            uint32_t stg = sb + (it & 3) * 16384;
            MMA_STAGE(stg);
            if (it + 3 < NIT) issue((it + 3) & 3, (it + 3) * 32);
            CP_COMMIT();
        }
        CP_WAIT(0);
        __syncthreads();   // pipeline smem dead; reuse as Stile

        float* Stile = (float*)sm;              // 128 x 130
        float* carrR = (float*)(sm + 66560);    // [4][64]  (later: E_chunk)
        float* carrI = carrR + 256;
        float* prefR = carrI + 256;             // [4][64]
        float* prefI = prefR + 256;

        // 1. accs -> Stile
#pragma unroll
        for (int mi = 0; mi < 2; ++mi) {
            int row = mBase + mi * 16 + g;
#pragma unroll
            for (int ni = 0; ni < 8; ++ni) {
                int col = nBase + ni * 8 + 2 * tig;
                *(float2*)(Stile + row * 130 + col) =
                    make_float2(acc[mi][ni][0], acc[mi][ni][1]);
                *(float2*)(Stile + (row + 8) * 130 + col) =
                    make_float2(acc[mi][ni][2], acc[mi][ni][3]);
            }
        }
        __syncthreads();

        // 2. segment-local scan (zero init), 4 segs x 64 complex cols
        const int pl = t & 63, seg = t >> 6;
        const int pg = (n0 >> 1) + pl;
        const float lr = g_lam_re[pg], li = g_lam_im[pg];
        {
            float yr = 0.f, yi = 0.f;
            float* colp = Stile + 2 * pl;
#pragma unroll 4
            for (int tt = 0; tt < 32; ++tt) {
                int row = seg * 32 + tt;
                float2 s = *(float2*)(colp + row * 130);
                float nyr = fmaf(lr, yr, fmaf(-li, yi, s.x));
                float nyi = fmaf(lr, yi, fmaf( li, yr, s.y));
                yr = nyr; yi = nyi;
                *(float2*)(colp + row * 130) = make_float2(yr, yi);
            }
            carrR[seg * 64 + pl] = yr;
            carrI[seg * 64 + pl] = yi;
        }
        __syncthreads();

        // 3. seg-carry combine -> chunk aggregate; publish; lookback.
        if (t < 64) {
            int pg2 = (n0 >> 1) + t;
            float l32r = g_lam32_re[pg2], l32i = g_lam32_im[pg2];
            float Pr = 0.f, Pi = 0.f;
            float sp[4][2];
#pragma unroll
            for (int q = 0; q < 4; ++q) {
                sp[q][0] = Pr; sp[q][1] = Pi;
                float cr = carrR[q * 64 + t], ci = carrI[q * 64 + t];
                float nPr = fmaf(l32r, Pr, fmaf(-l32i, Pi, cr));
                float nPi = fmaf(l32r, Pi, fmaf( l32i, Pr, ci));
                Pr = nPr; Pi = nPi;
            }
            size_t ci0 = (size_t)(bIdx * NCH + cIdx) * PDIM + pg2;
            *(float2*)(g_car + 2 * ci0) = make_float2(Pr, Pi);
            st_release_u32(g_flag + ci0, 1u);

            float Ecr = 0.f, Eci = 0.f;
            for (int j = 0; j < cIdx; ++j) {
                int d = cIdx - 1 - j;
                size_t fj = (size_t)(bIdx * NCH + j) * PDIM + pg2;
                while (ld_acquire_u32(g_flag + fj) == 0) { }
                float2 cv = ld_relaxed_f2(g_car + 2 * fj);
                float pr = g_powT_re[d][pg2], pi = g_powT_im[d][pg2];
                Ecr = fmaf(pr, cv.x, fmaf(-pi, cv.y, Ecr));
                Eci = fmaf(pr, cv.y, fmaf( pi, cv.x, Eci));
            }
#pragma unroll
            for (int q = 0; q < 4; ++q) {
                prefR[q * 64 + t] = sp[q][0];
                prefI[q * 64 + t] = sp[q][1];
            }
            carrR[t] = Ecr;
            carrI[t] = Eci;
        }
        __syncthreads();

        // 4. total prefix apply + fp16 convert, write final states to g_S16
        {
            float Ecr = carrR[pl], Eci = carrI[pl];
            float p32r = g_pow32_re[seg][pg], p32i = g_pow32_im[seg][pg];
            float Er = prefR[seg * 64 + pl] + p32r * Ecr - p32i * Eci;
            float Ei = prefI[seg * 64 + pl] + p32r * Eci + p32i * Ecr;
            float inv = g_inv_scl[pg];
            float wr = lr, wi = li;
            float* colp = Stile + 2 * pl;
            __half2* op = (__half2*)g_S16 + (size_t)m0 * PDIM + pg;
#pragma unroll 4
            for (int tt = 0; tt < 32; ++tt) {
                int row = seg * 32 + tt;
                float2 s = *(float2*)(colp + row * 130);
                float xr = fmaf(wr, Er, fmaf(-wi, Ei, s.x));
                float xi = fmaf(wr, Ei, fmaf( wi, Er, s.y));
                op[(size_t)row * PDIM] = __floats2half2_rn(xr * inv, xi * inv);
                float nwr = fmaf(wr, lr, -wi * li);
                float nwi = fmaf(wr, li,  wi * lr);
                wr = nwr; wi = nwi;
            }
        }
        // publish S16-chunk readiness
        __threadfence();
        __syncthreads();
        if (t == 0) red_release_add(g_done + mchunk, 1u);

    } else {
        // =================== GEMM3 ===================
        const int n0 = (role - 4) * 128;
        if (t == 0) {
            while (ld_acquire_u32(g_done + mchunk) != 4u) { }
        }
        __syncthreads();

        const __half* Ag = g_S16 + (size_t)(m0 + r0) * K3 + c0 * 8;
        const __half* Bg = g_Wc16 + (size_t)(n0 + r0) * K3 + c0 * 8;

        auto issue = [&](int slot, int kof) {
            uint32_t base = sb + slot * 16384;
            cp_async16(base + sAoff,        Ag + kof);
            cp_async16(base + sAoff + 4096, Ag + kof + (size_t)64 * K3);
            cp_async16(base + sAoff + 8192, Bg + kof);
            cp_async16(base + sAoff + 12288,Bg + kof + (size_t)64 * K3);
        };

        issue(0, 0);  CP_COMMIT();
        issue(1, 32); CP_COMMIT();
        issue(2, 64); CP_COMMIT();

        const int NIT = K3 / 32;   // 16
        for (int it = 0; it < NIT; ++it) {
            CP_WAIT(2);
            __syncthreads();
            uint32_t stg = sb + (it & 3) * 16384;
            MMA_STAGE(stg);
            if (it + 3 < NIT) issue((it + 3) & 3, (it + 3) * 32);
            CP_COMMIT();
        }

        // Epilogue with D*u feedthrough
#pragma unroll
        for (int mi = 0; mi < 2; ++mi) {
            int row0 = m0 + mBase + mi * 16 + g;
#pragma unroll
            for (int ni = 0; ni < 8; ++ni) {
                int col = n0 + nBase + ni * 8 + 2 * tig;
                float d0 = Dvec[col], d1 = Dvec[col + 1];
                float2 u0 = *(const float2*)(U + (size_t)row0 * HDIM + col);
                float2 u1 = *(const float2*)(U + (size_t)(row0 + 8) * HDIM + col);
                float2 v0 = make_float2(fmaf(d0, u0.x, acc[mi][ni][0]),
                                        fmaf(d1, u0.y, acc[mi][ni][1]));
                float2 v1 = make_float2(fmaf(d0, u1.x, acc[mi][ni][2]),
                                        fmaf(d1, u1.y, acc[mi][ni][3]));
                *(float2*)(C + (size_t)row0 * N3 + col) = v0;
                *(float2*)(C + (size_t)(row0 + 8) * N3 + col) = v1;
            }
        }
    }
}

// ---------------------------------------------------------------------------
extern "C" void kernel_launch(void* const* d_in, const int* in_sizes, int n_in,
                              void* d_out, int out_size)
{
    const float* u   = (const float*)d_in[0];
    const float* Lre = (const float*)d_in[1];
    const float* Lim = (const float*)d_in[2];
    const float* Bp  = (const float*)d_in[3];
    const float* Cp  = (const float*)d_in[4];
    const float* Dv  = (const float*)d_in[5];
    const float* lst = (const float*)d_in[6];
    float* out = (float*)d_out;

    cudaFuncSetAttribute(s5_fused,
                         cudaFuncAttributeMaxDynamicSharedMemorySize, FU_SMEM);

    // 1. single fully-parallel prep: u->fp16 + flags | pack (own coef) | tables
    s5_prep_kernel<<<2316, 256>>>(u, Bp, Cp, Lre, Lim, lst);

    // 2. fused: Bu GEMM + full scan + output GEMM (dataflow-synchronized)
    s5_fused<<<NMCH * 6, 256, FU_SMEM>>>(out, Dv, u);
}

// round 17
// speedup vs baseline: 1.7573x; 1.0384x over previous
#include <cuda_runtime.h>
#include <cuda_fp16.h>
#include <math.h>
#include <stdint.h>

// Problem dims
#define BSZ   16
#define LSEQ  1024
#define HDIM  256
#define PDIM  256
#define MROWS (BSZ*LSEQ)     // 16384
#define N1    (2*PDIM)       // 512  (interleaved re/im: col 2p, 2p+1)
#define K1    HDIM           // 256
#define N3    HDIM           // 256
#define K3    (2*PDIM)       // 512
#define CHUNK 128            // == GEMM tile M
#define NCH   (LSEQ/CHUNK)   // 8
#define NMCH  (MROWS/CHUNK)  // 128 m-chunks

// Scratch (static device memory; no allocations allowed)
__device__ __align__(128) __half g_S16[(size_t)MROWS * N1];  // 16 MB: final states fp16
__device__ __align__(128) __half g_u16[(size_t)MROWS * HDIM];// 8 MB: u in fp16
__device__ __align__(128) __half g_Wb16[N1 * K1];            // (512,256) N-major, K-contig
__device__ __align__(128) __half g_Wc16[N3 * K3];            // (256,512) N-major, K-contig
__device__ float g_lam_re[PDIM], g_lam_im[PDIM];
__device__ float g_lam32_re[PDIM], g_lam32_im[PDIM];         // lam^32
__device__ float g_pow32_re[4][PDIM], g_pow32_im[4][PDIM];   // lam^(32q)
__device__ float g_powT_re[NCH][PDIM], g_powT_im[NCH][PDIM]; // lam^(128j)
__device__ float g_inv_scl[PDIM];
__device__ __align__(128) float    g_car[BSZ * NCH * PDIM * 2]; // chunk aggregates
__device__ __align__(128) unsigned g_flag[BSZ * NCH * PDIM];    // per-p publish flags
__device__ __align__(128) unsigned g_done[NMCH];                // per-m-chunk S16-ready count

// ---------------------------------------------------------------------------
// helpers
// ---------------------------------------------------------------------------
__device__ __forceinline__ uint32_t smem_u32(const void* p) {
    uint32_t a;
    asm("{ .reg .u64 t; cvta.to.shared.u64 t, %1; cvt.u32.u64 %0, t; }" : "=r"(a) : "l"(p));
    return a;
}
__device__ __forceinline__ uint32_t f2h2(float a, float b) {   // lo=a, hi=b
    uint32_t r;
    asm("cvt.rn.f16x2.f32 %0, %1, %2;" : "=r"(r) : "f"(b), "f"(a));
    return r;
}
__device__ __forceinline__ void cp_async16(uint32_t saddr, const void* gaddr) {
    asm volatile("cp.async.cg.shared.global [%0], [%1], 16;" :: "r"(saddr), "l"(gaddr));
}
#define CP_COMMIT() asm volatile("cp.async.commit_group;" ::: "memory")
#define CP_WAIT(n)  asm volatile("cp.async.wait_group %0;" :: "n"(n) : "memory")

__device__ __forceinline__ void st_release_u32(unsigned* p, unsigned v) {
    asm volatile("st.release.gpu.global.u32 [%0], %1;" :: "l"(p), "r"(v) : "memory");
}
__device__ __forceinline__ unsigned ld_acquire_u32(const unsigned* p) {
    unsigned v;
    asm volatile("ld.acquire.gpu.global.u32 %0, [%1];" : "=r"(v) : "l"(p) : "memory");
    return v;
}
__device__ __forceinline__ void red_release_add(unsigned* p, unsigned v) {
    asm volatile("red.release.gpu.global.add.u32 [%0], %1;" :: "l"(p), "r"(v) : "memory");
}
__device__ __forceinline__ float2 ld_relaxed_f2(const float* p) {
    float2 v;
    asm volatile("ld.relaxed.gpu.global.v2.f32 {%0,%1}, [%2];"
                 : "=f"(v.x), "=f"(v.y) : "l"(p) : "memory");
    return v;
}

__device__ __forceinline__ void ldsm4(uint32_t& r0, uint32_t& r1, uint32_t& r2,
                                      uint32_t& r3, uint32_t addr) {
    asm volatile("ldmatrix.sync.aligned.m8n8.x4.shared.b16 {%0,%1,%2,%3}, [%4];"
                 : "=r"(r0), "=r"(r1), "=r"(r2), "=r"(r3) : "r"(addr));
}
__device__ __forceinline__ void mma16816(float c[4], const uint32_t a[4],
                                         uint32_t b0, uint32_t b1) {
    asm volatile(
        "mma.sync.aligned.m16n8k16.row.col.f32.f16.f16.f32 "
        "{%0,%1,%2,%3}, {%4,%5,%6,%7}, {%8,%9}, {%0,%1,%2,%3};"
        : "+f"(c[0]), "+f"(c[1]), "+f"(c[2]), "+f"(c[3])
        : "r"(a[0]), "r"(a[1]), "r"(a[2]), "r"(a[3]), "r"(b0), "r"(b1));
}

// MMA block on one 32-k stage.  ALL 12 ldsm issued up front (independent ->
// one latency exposure), then 32 back-to-back mma.  64B rows, chunk^((r>>1)&3).
#define MMA_STAGE(stgAddr)                                                    \
    do {                                                                      \
        uint32_t af[2][2][4], bf[2][4][4];                                    \
        _Pragma("unroll")                                                     \
        for (int ks = 0; ks < 2; ++ks) {                                      \
            const int cbase = ks * 2;                                         \
            _Pragma("unroll")                                                 \
            for (int mi = 0; mi < 2; ++mi) {                                  \
                int ml = mBase + mi * 16 + (lane & 15);                       \
                int ci = (cbase + (lane >> 4)) ^ ((ml >> 1) & 3);             \
                ldsm4(af[ks][mi][0], af[ks][mi][1], af[ks][mi][2],            \
                      af[ks][mi][3], (stgAddr) + ml * 64 + ci * 16);          \
            }                                                                 \
            _Pragma("unroll")                                                 \
            for (int nj = 0; nj < 4; ++nj) {                                  \
                int nl = nBase + nj * 16 + ((lane >> 4) & 1) * 8 + (lane & 7);\
                int ci = (cbase + ((lane >> 3) & 1)) ^ ((nl >> 1) & 3);       \
                ldsm4(bf[ks][nj][0], bf[ks][nj][1], bf[ks][nj][2],            \
                      bf[ks][nj][3], (stgAddr) + 8192 + nl * 64 + ci * 16);   \
            }                                                                 \
        }                                                                     \
        _Pragma("unroll")                                                     \
        for (int ks = 0; ks < 2; ++ks)                                        \
            _Pragma("unroll")                                                 \
            for (int mi = 0; mi < 2; ++mi)                                    \
                _Pragma("unroll")                                             \
                for (int nj = 0; nj < 4; ++nj) {                              \
                    mma16816(acc[mi][nj * 2 + 0], af[ks][mi],                 \
                             bf[ks][nj][0], bf[ks][nj][1]);                   \
                    mma16816(acc[mi][nj * 2 + 1], af[ks][mi],                 \
                             bf[ks][nj][2], bf[ks][nj][3]);                   \
                }                                                             \
    } while (0)

// ---------------------------------------------------------------------------
// ONE prep kernel, fully parallel (no serialized fp64 chains):
//   blocks [0,2048):     u -> fp16 + flag/done clear
//   blocks [2048,2304):  weight packing; block computes own coef[p]
//   blocks [2304,2316):  power tables via direct closed form, thread = p
// grid = 2316, block = 256.
// ---------------------------------------------------------------------------
__global__ void s5_prep_kernel(const float* __restrict__ u,
                               const float* __restrict__ Bp,
                               const float* __restrict__ Cp,
                               const float* __restrict__ Lre,
                               const float* __restrict__ Lim,
                               const float* __restrict__ lstep)
{
    if (blockIdx.x < 2048) {
        size_t i = ((size_t)blockIdx.x * 256 + threadIdx.x) * 8;
        float4 a = *(const float4*)(u + i);
        float4 b = *(const float4*)(u + i + 4);
        *(uint4*)(g_u16 + i) = make_uint4(f2h2(a.x, a.y), f2h2(a.z, a.w),
                                          f2h2(b.x, b.y), f2h2(b.z, b.w));
        if (blockIdx.x < 32) {
            ((uint4*)g_flag)[blockIdx.x * 256 + threadIdx.x] =
                make_uint4(0u, 0u, 0u, 0u);
        }
        if (blockIdx.x == 32 && threadIdx.x < NMCH) g_done[threadIdx.x] = 0u;
    } else if (blockIdx.x < 2304) {
        int p = blockIdx.x - 2048;
        int h = threadIdx.x;
        __shared__ float2 cfs;
        if (h == 0) {
            double lre = (double)Lre[p], lim = (double)Lim[p];
            double delta = exp((double)lstep[p]);
            double a = lre * delta, b = lim * delta;
            double ea = exp(a);
            double sb_, cb_;
            sincos(b, &sb_, &cb_);
            double lam_r = ea * cb_, lam_i = ea * sb_;
            double d2 = lre * lre + lim * lim;
            double nr = lam_r - 1.0, ni = lam_i;
            double cr = (nr * lre + ni * lim) / d2;
            double ci = (ni * lre - nr * lim) / d2;
            int e;
            frexp(sqrt(cr * cr + ci * ci), &e);
            double scl = ldexp(1.0, -e);
            cfs = make_float2((float)(cr * scl), (float)(ci * scl));
            g_inv_scl[p] = (float)ldexp(1.0, e);
        }
        __syncthreads();
        float2 cf = cfs;

        float br = Bp[((size_t)p * HDIM + h) * 2 + 0];
        float bi = Bp[((size_t)p * HDIM + h) * 2 + 1];
        g_Wb16[(size_t)(2 * p) * K1 + h]     = __float2half(cf.x * br - cf.y * bi);
        g_Wb16[(size_t)(2 * p + 1) * K1 + h] = __float2half(cf.x * bi + cf.y * br);

        float ccr = Cp[((size_t)h * PDIM + p) * 2 + 0];
        float cci = Cp[((size_t)h * PDIM + p) * 2 + 1];
        g_Wc16[(size_t)h * K3 + 2 * p]     = __float2half( 2.0f * ccr);
        g_Wc16[(size_t)h * K3 + 2 * p + 1] = __float2half(-2.0f * cci);
    } else {
        int e = blockIdx.x - 2304;          // 0..11
        if (e > 10) return;
        int p = threadIdx.x;

        double lre = (double)Lre[p], lim = (double)Lim[p];
        double delta = exp((double)lstep[p]);
        double a = lre * delta, b = lim * delta;

        double x;
        if (e == 0) x = 1.0;
        else if (e <= 3) x = 32.0 * e;
        else x = 128.0 * (e - 3);

        double ex = exp(x * a);
        double sb_, cb_;
        sincos(x * b, &sb_, &cb_);
        float vr = (float)(ex * cb_), vi = (float)(ex * sb_);

        if (e == 0) {
            g_lam_re[p] = vr;        g_lam_im[p] = vi;
            g_pow32_re[0][p] = 1.0f; g_pow32_im[0][p] = 0.0f;
            g_powT_re[0][p] = 1.0f;  g_powT_im[0][p] = 0.0f;
        } else if (e <= 3) {
            g_pow32_re[e][p] = vr;  g_pow32_im[e][p] = vi;
            if (e == 1) { g_lam32_re[p] = vr; g_lam32_im[p] = vi; }
        } else {
            g_powT_re[e - 3][p] = vr;
            g_powT_im[e - 3][p] = vi;
        }
    }
}

// ---------------------------------------------------------------------------
// FUSED kernel: 768 blocks, 6 roles per m-chunk: r<4 GEMM1+scan, r>=4 GEMM3.
// 6-slot cp.async ring, TWO k32 stages per wait+sync (4-deep prefetch).
// Dataflow-synchronized via per-m-chunk release counters.
// ---------------------------------------------------------------------------
#define FU_SMEM 98304   // 6 x 16KB ring; epilogue needs 70656

__global__ void __launch_bounds__(256, 2)
s5_fused(float* __restrict__ C,
         const float* __restrict__ Dvec,
         const float* __restrict__ U)
{
    extern __shared__ char sm[];
    uint32_t sb = smem_u32(sm);

    const int bid = blockIdx.x;
    const int mchunk = bid / 6;
    const int role = bid % 6;

    const int t = threadIdx.x;
    const int lane = t & 31, w = t >> 5;
    const int g = lane >> 2, tig = lane & 3;
    const int mBase = (w & 3) * 32;
    const int nBase = (w >> 2) * 64;
    const int m0 = mchunk * 128;

    const int r0 = t >> 2, c0 = t & 3;
    const uint32_t sAoff = r0 * 64 + (((uint32_t)(c0 ^ ((r0 >> 1) & 3))) << 4);

    float acc[2][8][4];
#pragma unroll
    for (int mi = 0; mi < 2; ++mi)
#pragma unroll
        for (int ni = 0; ni < 8; ++ni)
#pragma unroll
            for (int q = 0; q < 4; ++q) acc[mi][ni][q] = 0.0f;

    if (role < 4) {
        // =================== GEMM1 + fused scan ===================
        const int n0 = role * 128;
        const int bIdx = m0 >> 10, cIdx = (m0 >> 7) & (NCH - 1);
        const __half* Ag = g_u16 + (size_t)(m0 + r0) * K1 + c0 * 8;
        const __half* Bg = g_Wb16 + (size_t)(n0 + r0) * K1 + c0 * 8;

        auto issue = [&](int slot, int kof) {
            uint32_t base = sb + slot * 16384;
            cp_async16(base + sAoff,        Ag + kof);
            cp_async16(base + sAoff + 4096, Ag + kof + (size_t)64 * K1);
            cp_async16(base + sAoff + 8192, Bg + kof);
            cp_async16(base + sAoff + 12288,Bg + kof + (size_t)64 * K1);
        };

        issue(0, 0);  CP_COMMIT();
        issue(1, 32); CP_COMMIT();
        issue(2, 64); CP_COMMIT();
        issue(3, 96); CP_COMMIT();

        const int NIT = K1 / 32;    // 8 stages
        const int NJ  = NIT / 2;    // 4 iterations
#pragma unroll
        for (int j = 0; j < NJ; ++j) {
            if (j == NJ - 1) { CP_WAIT(0); } else { CP_WAIT(2); }
            __syncthreads();
            MMA_STAGE(sb + ((2 * j) % 6) * 16384);
            MMA_STAGE(sb + ((2 * j + 1) % 6) * 16384);
            int st = 2 * j + 4;
            if (st < NIT)     { issue(st % 6, st * 32);           CP_COMMIT(); }
            if (st + 1 < NIT) { issue((st + 1) % 6, (st + 1) * 32); CP_COMMIT(); }
        }
        __syncthreads();   // pipeline smem dead; reuse as Stile

        float* Stile = (float*)sm;              // 128 x 130
        float* carrR = (float*)(sm + 66560);    // [4][64]  (later: E_chunk)
        float* carrI = carrR + 256;
        float* prefR = carrI + 256;             // [4][64]
        float* prefI = prefR + 256;

        // 1. accs -> Stile
#pragma unroll
        for (int mi = 0; mi < 2; ++mi) {
            int row = mBase + mi * 16 + g;
#pragma unroll
            for (int ni = 0; ni < 8; ++ni) {
                int col = nBase + ni * 8 + 2 * tig;
                *(float2*)(Stile + row * 130 + col) =
                    make_float2(acc[mi][ni][0], acc[mi][ni][1]);
                *(float2*)(Stile + (row + 8) * 130 + col) =
                    make_float2(acc[mi][ni][2], acc[mi][ni][3]);
            }
        }
        __syncthreads();

        // 2. segment-local scan (zero init), 4 segs x 64 complex cols
        const int pl = t & 63, seg = t >> 6;
        const int pg = (n0 >> 1) + pl;
        const float lr = g_lam_re[pg], li = g_lam_im[pg];
        {
            float yr = 0.f, yi = 0.f;
            float* colp = Stile + 2 * pl;
#pragma unroll 4
            for (int tt = 0; tt < 32; ++tt) {
                int row = seg * 32 + tt;
                float2 s = *(float2*)(colp + row * 130);
                float nyr = fmaf(lr, yr, fmaf(-li, yi, s.x));
                float nyi = fmaf(lr, yi, fmaf( li, yr, s.y));
                yr = nyr; yi = nyi;
                *(float2*)(colp + row * 130) = make_float2(yr, yi);
            }
            carrR[seg * 64 + pl] = yr;
            carrI[seg * 64 + pl] = yi;
        }
        __syncthreads();

        // 3. seg-carry combine -> chunk aggregate; publish; lookback.
        if (t < 64) {
            int pg2 = (n0 >> 1) + t;
            float l32r = g_lam32_re[pg2], l32i = g_lam32_im[pg2];
            float Pr = 0.f, Pi = 0.f;
            float sp[4][2];
#pragma unroll
            for (int q = 0; q < 4; ++q) {
                sp[q][0] = Pr; sp[q][1] = Pi;
                float cr = carrR[q * 64 + t], ci = carrI[q * 64 + t];
                float nPr = fmaf(l32r, Pr, fmaf(-l32i, Pi, cr));
                float nPi = fmaf(l32r, Pi, fmaf( l32i, Pr, ci));
                Pr = nPr; Pi = nPi;
            }
            size_t ci0 = (size_t)(bIdx * NCH + cIdx) * PDIM + pg2;
            *(float2*)(g_car + 2 * ci0) = make_float2(Pr, Pi);
            st_release_u32(g_flag + ci0, 1u);

            float Ecr = 0.f, Eci = 0.f;
            for (int j = 0; j < cIdx; ++j) {
                int d = cIdx - 1 - j;
                size_t fj = (size_t)(bIdx * NCH + j) * PDIM + pg2;
                while (ld_acquire_u32(g_flag + fj) == 0) { }
                float2 cv = ld_relaxed_f2(g_car + 2 * fj);
                float pr = g_powT_re[d][pg2], pi = g_powT_im[d][pg2];
                Ecr = fmaf(pr, cv.x, fmaf(-pi, cv.y, Ecr));
                Eci = fmaf(pr, cv.y, fmaf( pi, cv.x, Eci));
            }
#pragma unroll
            for (int q = 0; q < 4; ++q) {
                prefR[q * 64 + t] = sp[q][0];
                prefI[q * 64 + t] = sp[q][1];
            }
            carrR[t] = Ecr;
            carrI[t] = Eci;
        }
        __syncthreads();

        // 4. total prefix apply + fp16 convert, write final states to g_S16
        {
            float Ecr = carrR[pl], Eci = carrI[pl];
            float p32r = g_pow32_re[seg][pg], p32i = g_pow32_im[seg][pg];
            float Er = prefR[seg * 64 + pl] + p32r * Ecr - p32i * Eci;
            float Ei = prefI[seg * 64 + pl] + p32r * Eci + p32i * Ecr;
            float inv = g_inv_scl[pg];
            float wr = lr, wi = li;
            float* colp = Stile + 2 * pl;
            __half2* op = (__half2*)g_S16 + (size_t)m0 * PDIM + pg;
#pragma unroll 4
            for (int tt = 0; tt < 32; ++tt) {
                int row = seg * 32 + tt;
                float2 s = *(float2*)(colp + row * 130);
                float xr = fmaf(wr, Er, fmaf(-wi, Ei, s.x));
                float xi = fmaf(wr, Ei, fmaf( wi, Er, s.y));
                op[(size_t)row * PDIM] = __floats2half2_rn(xr * inv, xi * inv);
                float nwr = fmaf(wr, lr, -wi * li);
                float nwi = fmaf(wr, li,  wi * lr);
                wr = nwr; wi = nwi;
            }
        }
        // publish S16-chunk readiness
        __threadfence();
        __syncthreads();
        if (t == 0) red_release_add(g_done + mchunk, 1u);

    } else {
        // =================== GEMM3 ===================
        const int n0 = (role - 4) * 128;
        if (t == 0) {
            while (ld_acquire_u32(g_done + mchunk) != 4u) { }
        }
        __syncthreads();

        const __half* Ag = g_S16 + (size_t)(m0 + r0) * K3 + c0 * 8;
        const __half* Bg = g_Wc16 + (size_t)(n0 + r0) * K3 + c0 * 8;

        auto issue = [&](int slot, int kof) {
            uint32_t base = sb + slot * 16384;
            cp_async16(base + sAoff,        Ag + kof);
            cp_async16(base + sAoff + 4096, Ag + kof + (size_t)64 * K3);
            cp_async16(base + sAoff + 8192, Bg + kof);
            cp_async16(base + sAoff + 12288,Bg + kof + (size_t)64 * K3);
        };

        issue(0, 0);  CP_COMMIT();
        issue(1, 32); CP_COMMIT();
        issue(2, 64); CP_COMMIT();
        issue(3, 96); CP_COMMIT();

        const int NIT = K3 / 32;    // 16 stages
        const int NJ  = NIT / 2;    // 8 iterations
#pragma unroll
        for (int j = 0; j < NJ; ++j) {
            if (j == NJ - 1) { CP_WAIT(0); } else { CP_WAIT(2); }
            __syncthreads();
            MMA_STAGE(sb + ((2 * j) % 6) * 16384);
            MMA_STAGE(sb + ((2 * j + 1) % 6) * 16384);
            int st = 2 * j + 4;
            if (st < NIT)     { issue(st % 6, st * 32);             CP_COMMIT(); }
            if (st + 1 < NIT) { issue((st + 1) % 6, (st + 1) * 32); CP_COMMIT(); }
        }

        // Epilogue with D*u feedthrough
#pragma unroll
        for (int mi = 0; mi < 2; ++mi) {
            int row0 = m0 + mBase + mi * 16 + g;
#pragma unroll
            for (int ni = 0; ni < 8; ++ni) {
                int col = n0 + nBase + ni * 8 + 2 * tig;
                float d0 = Dvec[col], d1 = Dvec[col + 1];
                float2 u0 = *(const float2*)(U + (size_t)row0 * HDIM + col);
                float2 u1 = *(const float2*)(U + (size_t)(row0 + 8) * HDIM + col);
                float2 v0 = make_float2(fmaf(d0, u0.x, acc[mi][ni][0]),
                                        fmaf(d1, u0.y, acc[mi][ni][1]));
                float2 v1 = make_float2(fmaf(d0, u1.x, acc[mi][ni][2]),
                                        fmaf(d1, u1.y, acc[mi][ni][3]));
                *(float2*)(C + (size_t)row0 * N3 + col) = v0;
                *(float2*)(C + (size_t)(row0 + 8) * N3 + col) = v1;
            }
        }
    }
}

// ---------------------------------------------------------------------------
extern "C" void kernel_launch(void* const* d_in, const int* in_sizes, int n_in,
                              void* d_out, int out_size)
{
    const float* u   = (const float*)d_in[0];
    const float* Lre = (const float*)d_in[1];
    const float* Lim = (const float*)d_in[2];
    const float* Bp  = (const float*)d_in[3];
    const float* Cp  = (const float*)d_in[4];
    const float* Dv  = (const float*)d_in[5];
    const float* lst = (const float*)d_in[6];
    float* out = (float*)d_out;

    cudaFuncSetAttribute(s5_fused,
                         cudaFuncAttributeMaxDynamicSharedMemorySize, FU_SMEM);

    // 1. single fully-parallel prep: u->fp16 + flags | pack (own coef) | tables
    s5_prep_kernel<<<2316, 256>>>(u, Bp, Cp, Lre, Lim, lst);

    // 2. fused: Bu GEMM + full scan + output GEMM (dataflow-synchronized)
    s5_fused<<<NMCH * 6, 256, FU_SMEM>>>(out, Dv, u);
}